// round 11
// baseline (speedup 1.0000x reference)
#include <cuda_runtime.h>
#include <math.h>

// ---------------------------------------------------------------------------
// VQ-VAE forward. Encoder: compensated TF32 mma (error ~1e-6, argmin-safe).
// Decoder: single-pass TF32 mma with pre-converted smem operands.
// BN fused into consumers; exact fp32 VQ argmin.
// ---------------------------------------------------------------------------

#define BB 64
static const float BN_EPS = 1e-5f;

// ------------------------- scratch (device globals) ------------------------
__device__ float g_a1[64 * 16 * 128 * 128];
__device__ float g_a2[64 * 32 * 64 * 64];
__device__ float g_a3[64 * 64 * 32 * 32];
__device__ float g_q [64 * 64 * 32 * 32];
__device__ float g_d1[64 * 32 * 64 * 64];
__device__ float g_d2[64 * 16 * 128 * 128];

__device__ int    g_idx[65536];
__device__ float  g_codeNorm[512];
__device__ float2 g_part[64 * 32];
__device__ float  g_bnSc[6 * 64];
__device__ float  g_bnSh[6 * 64];
__device__ float  g_lossPart[512];

// ---------------------------- tf32 mma helpers -----------------------------
__device__ __forceinline__ unsigned int f2tf(float x) {
    unsigned int r;
    asm("cvt.rna.tf32.f32 %0, %1;" : "=r"(r) : "f"(x));
    return r;
}
__device__ __forceinline__ void mma_tf32(float* c, const unsigned int* a,
                                         const unsigned int* b) {
    asm volatile(
        "mma.sync.aligned.m16n8k8.row.col.f32.tf32.tf32.f32 "
        "{%0,%1,%2,%3}, {%4,%5,%6,%7}, {%8,%9}, {%0,%1,%2,%3};"
        : "+f"(c[0]), "+f"(c[1]), "+f"(c[2]), "+f"(c[3])
        : "r"(a[0]), "r"(a[1]), "r"(a[2]), "r"(a[3]), "r"(b[0]), "r"(b[1]));
}

// -------------------- conv k4 s2 p1 via compensated TF32 mma ---------------
// GEMM per tap-group (ky, kxb): K = 8 = 4 ci x 2 b (kx = kxb + 2b).
// Block (256 thr / 8 warps) = 16x16 output tile of one image.
// Warp w: rows y = 2w, 2w+1 (2 m16-tiles, m = x). NT n-tiles of 8 co.
// Compensation: D += Ahi*Bhi + Alo*Bhi + Ahi*Blo  (~fp32 accuracy).
template <int CIN, int COUT, int NT, int HIN, int WIN, bool FUSE>
__global__ __launch_bounds__(256)
void conv_mma(const float* __restrict__ in, const float* __restrict__ w,
              const float* __restrict__ bias, float* __restrict__ out,
              const float* __restrict__ bnsc, const float* __restrict__ bnsh)
{
    constexpr int HOUT = HIN / 2, WOUT = WIN / 2;
    constexpr int NBX = WOUT / 16, NBY = HOUT / 16;
    constexpr int COPAD = NT * 8 + 8;
    constexpr int PS = 34 * 36 + 1;          // per-ci plane stride (odd)

    extern __shared__ unsigned int dyn[];
    unsigned int* tHi = dyn;                 // 4 * PS
    unsigned int* tLo = dyn + 4 * PS;
    unsigned int* wHi = dyn + 8 * PS;        // 8 tg * 8 k * COPAD
    unsigned int* wLo = wHi + 64 * COPAD;

    const int b  = blockIdx.x;
    const int tx = b % NBX;
    const int ty = (b / NBX) % NBY;
    const int n  = b / (NBX * NBY);
    const int cog = blockIdx.y * NT * 8;

    const int lane = threadIdx.x & 31;
    const int wid  = threadIdx.x >> 5;
    const int mrow = lane >> 2;
    const int kcol = lane & 3;
    const int ciL  = kcol >> 1;
    const int bL   = kcol & 1;

    const int X0 = tx * 32 - 1, Y0 = ty * 32 - 1;
    const float* inn = in + (long long)n * CIN * HIN * WIN;

    float acc[2][NT][4];
    #pragma unroll
    for (int nt = 0; nt < NT; nt++) {
        const float b0 = __ldg(&bias[cog + nt * 8 + 2 * kcol]);
        const float b1 = __ldg(&bias[cog + nt * 8 + 2 * kcol + 1]);
        #pragma unroll
        for (int mt = 0; mt < 2; mt++) {
            acc[mt][nt][0] = b0; acc[mt][nt][1] = b1;
            acc[mt][nt][2] = b0; acc[mt][nt][3] = b1;
        }
    }

    for (int ci0 = 0; ci0 < CIN; ci0 += 4) {
        __syncthreads();
        // stage input patch 34x34 (4 ci planes), split hi/lo tf32
        for (int t = threadIdx.x; t < 4 * 34 * 34; t += 256) {
            const int c  = t / (34 * 34);
            const int r  = (t / 34) % 34;
            const int cc = t % 34;
            const int gy = Y0 + r, gx = X0 + cc;
            const bool ok = (ci0 + c < CIN) &&
                            ((unsigned)gy < (unsigned)HIN) &&
                            ((unsigned)gx < (unsigned)WIN);
            float v = ok ?
                __ldg(&inn[((long long)(ci0 + c) * HIN + gy) * WIN + gx]) : 0.f;
            if (FUSE && ok)
                v = fmaxf(0.f, fmaf(v, bnsc[ci0 + c], bnsh[ci0 + c]));
            const unsigned int hi = f2tf(v);
            tHi[c * PS + r * 36 + cc] = hi;
            tLo[c * PS + r * 36 + cc] = f2tf(v - __uint_as_float(hi));
        }
        // stage weights: [tg=(ky,kxb)][k=ci*2+b][coPad], split hi/lo
        for (int t = threadIdx.x; t < 64 * COPAD; t += 256) {
            const int co = t % COPAD;
            const int k8 = (t / COPAD) & 7;
            const int tg = t / (COPAD * 8);
            const int ci = k8 >> 1, bb = k8 & 1;
            const int ky = tg >> 1, kxb = tg & 1;
            float v = 0.f;
            if (co < NT * 8 && cog + co < COUT && ci0 + ci < CIN)
                v = __ldg(&w[((cog + co) * CIN + ci0 + ci) * 16 +
                             ky * 4 + kxb + 2 * bb]);
            const unsigned int hi = f2tf(v);
            wHi[t] = hi;
            wLo[t] = f2tf(v - __uint_as_float(hi));
        }
        __syncthreads();

        #pragma unroll
        for (int tg = 0; tg < 8; tg++) {
            const int ky = tg >> 1, kxb = tg & 1;
            const int kx = kxb + 2 * bL;
            const int col0 = 2 * mrow + kx;
            unsigned int Ah[2][4], Al[2][4];
            #pragma unroll
            for (int mt = 0; mt < 2; mt++) {
                const int rbase = (2 * (2 * wid + mt) + ky) * 36;
                const int i00 = ciL * PS + rbase + col0;
                const int i20 = (ciL + 2) * PS + rbase + col0;
                Ah[mt][0] = tHi[i00];      Al[mt][0] = tLo[i00];
                Ah[mt][1] = tHi[i00 + 16]; Al[mt][1] = tLo[i00 + 16];
                Ah[mt][2] = tHi[i20];      Al[mt][2] = tLo[i20];
                Ah[mt][3] = tHi[i20 + 16]; Al[mt][3] = tLo[i20 + 16];
            }
            #pragma unroll
            for (int nt = 0; nt < NT; nt++) {
                const int coL = nt * 8 + mrow;
                const int wb = tg * 8 * COPAD + kcol * COPAD + coL;
                unsigned int Bh[2], Bl[2];
                Bh[0] = wHi[wb];              Bl[0] = wLo[wb];
                Bh[1] = wHi[wb + 4 * COPAD];  Bl[1] = wLo[wb + 4 * COPAD];
                #pragma unroll
                for (int mt = 0; mt < 2; mt++) {
                    mma_tf32(acc[mt][nt], Ah[mt], Bh);
                    mma_tf32(acc[mt][nt], Al[mt], Bh);
                    mma_tf32(acc[mt][nt], Ah[mt], Bl);
                }
            }
        }
    }

    // writeback: C[m=x][n=co]; c0:(mrow, 2kcol) c1:+1 c2:(mrow+8) c3:+1
    #pragma unroll
    for (int mt = 0; mt < 2; mt++) {
        const int oy = ty * 16 + 2 * wid + mt;
        const int ox = tx * 16 + mrow;
        #pragma unroll
        for (int nt = 0; nt < NT; nt++) {
            const int co = cog + nt * 8 + 2 * kcol;
            float* p0 = out + (((long long)n * COUT + co) * HOUT + oy) * WOUT;
            float* p1 = out + (((long long)n * COUT + co + 1) * HOUT + oy) * WOUT;
            p0[ox]     = acc[mt][nt][0];
            p1[ox]     = acc[mt][nt][1];
            p0[ox + 8] = acc[mt][nt][2];
            p1[ox + 8] = acc[mt][nt][3];
        }
    }
}

// --------------------- deconv k4 s2 p1 via TF32 mma ------------------------
// Operands pre-converted to tf32 at staging (no cvt in mainloop).
template <int CIN, int COUT, int NT, int KC, int HIN, int WIN, bool FUSE>
__global__ __launch_bounds__(256)
void deconv_mma(const float* __restrict__ in, const float* __restrict__ w,
                const float* __restrict__ bias, float* __restrict__ out,
                const float* __restrict__ bnsc, const float* __restrict__ bnsh)
{
    constexpr int COPAD = COUT + 8;
    constexpr int HOUT = 2 * HIN, WOUT = 2 * WIN;
    constexpr int NBX = WIN / 16, NBY = HIN / 8;

    __shared__ unsigned int tile[KC][10][20];
    __shared__ unsigned int wB[16 * KC * COPAD];

    const int b  = blockIdx.x;
    const int tx = b % NBX;
    const int ty = (b / NBX) % NBY;
    const int n  = b / (NBX * NBY);
    const int X0 = tx * 16, Y0 = ty * 8;

    const int lane = threadIdx.x & 31;
    const int wid  = threadIdx.x >> 5;
    const int px = wid & 1, py = (wid >> 1) & 1, h = wid >> 2;

    const float* inn = in + (long long)n * CIN * HIN * WIN;

    float acc[4][NT][4];
    #pragma unroll
    for (int nt = 0; nt < NT; nt++) {
        const int co0 = nt * 8 + 2 * (lane & 3);
        const float b0 = (co0     < COUT) ? __ldg(&bias[co0])     : 0.f;
        const float b1 = (co0 + 1 < COUT) ? __ldg(&bias[co0 + 1]) : 0.f;
        #pragma unroll
        for (int mt = 0; mt < 4; mt++) {
            acc[mt][nt][0] = b0; acc[mt][nt][1] = b1;
            acc[mt][nt][2] = b0; acc[mt][nt][3] = b1;
        }
    }

    for (int ci0 = 0; ci0 < CIN; ci0 += KC) {
        __syncthreads();
        for (int t = threadIdx.x; t < 16 * KC * COPAD; t += 256) {
            const int co  = t % COPAD;
            const int rem = t / COPAD;
            const int ci  = rem % KC;
            const int tap = rem / KC;
            const float v = (co < COUT) ?
                __ldg(&w[(co * CIN + ci0 + ci) * 16 + tap]) : 0.f;
            wB[t] = f2tf(v);
        }
        for (int t = threadIdx.x; t < KC * 10 * 18; t += 256) {
            const int cc  = t % 18;
            const int rem = t / 18;
            const int r   = rem % 10;
            const int c   = rem / 10;
            const int gy = Y0 - 1 + r, gx = X0 - 1 + cc;
            const bool ok = ((unsigned)gy < (unsigned)HIN) &&
                            ((unsigned)gx < (unsigned)WIN);
            float v = ok ?
                __ldg(&inn[((long long)(ci0 + c) * HIN + gy) * WIN + gx]) : 0.f;
            if (FUSE && ok)
                v = fmaxf(0.f, fmaf(v, bnsc[ci0 + c], bnsh[ci0 + c]));
            tile[c][r][cc] = f2tf(v);
        }
        __syncthreads();

        #pragma unroll
        for (int a = 0; a < 2; a++) {
            #pragma unroll
            for (int bs = 0; bs < 2; bs++) {
                const int tap = (py + 2 * a) * 4 + (px + 2 * bs);
                const unsigned int* wT = &wB[tap * KC * COPAD];
                const int xA = (lane >> 2) + px + bs;
                #pragma unroll
                for (int kk = 0; kk < KC / 8; kk++) {
                    const int kA = kk * 8 + (lane & 3);
                    unsigned int A[4][4];
                    #pragma unroll
                    for (int mt = 0; mt < 4; mt++) {
                        const int yA = h * 4 + mt + py + a;
                        A[mt][0] = tile[kA][yA][xA];
                        A[mt][1] = tile[kA][yA][xA + 8];
                        A[mt][2] = tile[kA + 4][yA][xA];
                        A[mt][3] = tile[kA + 4][yA][xA + 8];
                    }
                    #pragma unroll
                    for (int nt = 0; nt < NT; nt++) {
                        unsigned int Bf[2];
                        const int coL = nt * 8 + (lane >> 2);
                        Bf[0] = wT[kA * COPAD + coL];
                        Bf[1] = wT[(kA + 4) * COPAD + coL];
                        #pragma unroll
                        for (int mt = 0; mt < 4; mt++)
                            mma_tf32(acc[mt][nt], A[mt], Bf);
                    }
                }
            }
        }
    }

    #pragma unroll
    for (int mt = 0; mt < 4; mt++) {
        const int orow = 2 * (Y0 + h * 4 + mt) + py;
        const int qx0 = lane >> 2;
        const int ox0 = 2 * (X0 + qx0) + px;
        const int ox1 = 2 * (X0 + qx0 + 8) + px;
        #pragma unroll
        for (int nt = 0; nt < NT; nt++) {
            const int co0 = nt * 8 + 2 * (lane & 3);
            if (co0 < COUT) {
                float* rowp = out + (((long long)n * COUT + co0) * HOUT + orow) * WOUT;
                rowp[ox0] = acc[mt][nt][0];
                rowp[ox1] = acc[mt][nt][2];
            }
            if (co0 + 1 < COUT) {
                float* rowp = out + (((long long)n * COUT + co0 + 1) * HOUT + orow) * WOUT;
                rowp[ox0] = acc[mt][nt][1];
                rowp[ox1] = acc[mt][nt][3];
            }
        }
    }
}

// ------------------------------- batchnorm ---------------------------------
__global__ __launch_bounds__(256)
void bn_stats(const float* __restrict__ x, int C, int HW)
{
    const int c = blockIdx.x >> 5;
    const int s = blockIdx.x & 31;
    const int chunk4 = HW >> 7;

    float sum = 0.f, sq = 0.f;
    for (int n = 0; n < BB; n++) {
        const float4* base = (const float4*)(x + ((long long)(n * C + c)) * HW) +
                             s * chunk4;
        for (int p = threadIdx.x; p < chunk4; p += 256) {
            float4 v = base[p];
            sum += v.x + v.y + v.z + v.w;
            sq = fmaf(v.x, v.x, sq); sq = fmaf(v.y, v.y, sq);
            sq = fmaf(v.z, v.z, sq); sq = fmaf(v.w, v.w, sq);
        }
    }
    __shared__ float s1[256], s2[256];
    s1[threadIdx.x] = sum; s2[threadIdx.x] = sq;
    __syncthreads();
    for (int off = 128; off; off >>= 1) {
        if (threadIdx.x < off) {
            s1[threadIdx.x] += s1[threadIdx.x + off];
            s2[threadIdx.x] += s2[threadIdx.x + off];
        }
        __syncthreads();
    }
    if (threadIdx.x == 0) g_part[blockIdx.x] = make_float2(s1[0], s2[0]);
}

__global__ void bn_finalize(const float* __restrict__ gam,
                            const float* __restrict__ bet, int HW,
                            float* __restrict__ outSc, float* __restrict__ outSh)
{
    const int c = blockIdx.x;
    float2 p = g_part[c * 32 + threadIdx.x];
    double S = p.x, Q = p.y;
    for (int off = 16; off; off >>= 1) {
        S += __shfl_down_sync(0xffffffffu, S, off);
        Q += __shfl_down_sync(0xffffffffu, Q, off);
    }
    if (threadIdx.x == 0) {
        const double P = (double)BB * (double)HW;
        const double mean = S / P;
        const double var  = Q / P - mean * mean;
        const float rstd  = (float)(1.0 / sqrt(var + (double)BN_EPS));
        const float sc = gam[c] * rstd;
        outSc[c] = sc;
        outSh[c] = bet[c] - (float)mean * sc;
    }
}

__global__ __launch_bounds__(256)
void bn_apply_tanh(float* __restrict__ x, int C, int HW, int total4,
                   const float* __restrict__ sc_, const float* __restrict__ sh_)
{
    const int i = blockIdx.x * 256 + threadIdx.x;
    if (i >= total4) return;
    const int hw4 = HW >> 2;
    const int c = (i / hw4) % C;
    const float sc = sc_[c], sh = sh_[c];
    float4 v = ((float4*)x)[i];
    v.x = tanhf(fmaf(v.x, sc, sh)); v.y = tanhf(fmaf(v.y, sc, sh));
    v.z = tanhf(fmaf(v.z, sc, sh)); v.w = tanhf(fmaf(v.w, sc, sh));
    ((float4*)x)[i] = v;
}

// ---------------------------------- VQ -------------------------------------
__global__ void code_norms(const float* __restrict__ cb)
{
    const int k = threadIdx.x;
    float s = 0.f;
    const float* r = cb + k * 64;
    #pragma unroll
    for (int d = 0; d < 64; d++) s = fmaf(r[d], r[d], s);
    g_codeNorm[k] = s;
}

__global__ __launch_bounds__(128)
void vq_argmin(const float* __restrict__ ze, const float* __restrict__ cb,
               const float* __restrict__ sc_, const float* __restrict__ sh_)
{
    __shared__ float sc[64 * 64];
    __shared__ float scn[64];
    __shared__ float red[128];
    __shared__ float ssc[64], ssh[64];

    if (threadIdx.x < 64) {
        ssc[threadIdx.x] = sc_[threadIdx.x];
        ssh[threadIdx.x] = sh_[threadIdx.x];
    }
    __syncthreads();

    const int idx = blockIdx.x * 128 + threadIdx.x;
    const int n  = idx >> 10;
    const int hw = idx & 1023;
    const float* base = ze + (long long)n * 64 * 1024 + hw;

    float z[64];
    #pragma unroll
    for (int d = 0; d < 64; d++)
        z[d] = fmaxf(0.f, fmaf(base[d * 1024], ssc[d], ssh[d]));
    float zz = 0.f;
    #pragma unroll
    for (int d = 0; d < 64; d++) zz = fmaf(z[d], z[d], zz);

    float best = 3.4e38f;
    int   bi   = 0;
    for (int ch = 0; ch < 8; ch++) {
        __syncthreads();
        for (int t = threadIdx.x; t < 1024; t += 128)
            ((float4*)sc)[t] = ((const float4*)(cb + ch * 4096))[t];
        if (threadIdx.x < 64) scn[threadIdx.x] = g_codeNorm[ch * 64 + threadIdx.x];
        __syncthreads();
        #pragma unroll 2
        for (int j = 0; j < 64; j++) {
            const float4* cp = (const float4*)&sc[j * 64];
            float dot = 0.f;
            #pragma unroll
            for (int d4 = 0; d4 < 16; d4++) {
                float4 c4 = cp[d4];
                dot = fmaf(z[4*d4+0], c4.x, dot);
                dot = fmaf(z[4*d4+1], c4.y, dot);
                dot = fmaf(z[4*d4+2], c4.z, dot);
                dot = fmaf(z[4*d4+3], c4.w, dot);
            }
            const float dist = zz - 2.f * dot + scn[j];
            const int k = ch * 64 + j;
            if (dist < best) { best = dist; bi = k; }
        }
    }
    g_idx[idx] = bi;

    const float* cr = cb + bi * 64;
    float e = 0.f;
    #pragma unroll
    for (int d = 0; d < 64; d++) { float df = z[d] - cr[d]; e = fmaf(df, df, e); }

    red[threadIdx.x] = e;
    __syncthreads();
    for (int off = 64; off; off >>= 1) {
        if (threadIdx.x < off) red[threadIdx.x] += red[threadIdx.x + off];
        __syncthreads();
    }
    if (threadIdx.x == 0) g_lossPart[blockIdx.x] = red[0];
}

__global__ void vq_loss_final(float* __restrict__ loss_out)
{
    __shared__ double red[512];
    red[threadIdx.x] = (double)g_lossPart[threadIdx.x];
    __syncthreads();
    for (int off = 256; off; off >>= 1) {
        if (threadIdx.x < off) red[threadIdx.x] += red[threadIdx.x + off];
        __syncthreads();
    }
    if (threadIdx.x == 0)
        loss_out[0] = (float)(2.0 * red[0] / (65536.0 * 64.0));
}

__global__ __launch_bounds__(256)
void vq_scatter(float* __restrict__ q, const float* __restrict__ cb)
{
    const int i = blockIdx.x * 256 + threadIdx.x;
    const int hw = i & 1023;
    const int d  = (i >> 10) & 63;
    const int n  = i >> 16;
    const int code = g_idx[n * 1024 + hw];
    q[i] = cb[code * 64 + d];
}

// -------------------------------- launch -----------------------------------
static inline int nblk(long long total) { return (int)((total + 255) / 256); }

extern "C" void kernel_launch(void* const* d_in, const int* in_sizes, int n_in,
                              void* d_out, int out_size)
{
    (void)in_sizes; (void)n_in;
    const float* x    = (const float*)d_in[0];
    const float* cb   = (const float*)d_in[1];
    const float* eW1  = (const float*)d_in[2];
    const float* eb1  = (const float*)d_in[3];
    const float* eg1  = (const float*)d_in[4];
    const float* ebt1 = (const float*)d_in[5];
    const float* eW2  = (const float*)d_in[6];
    const float* eb2  = (const float*)d_in[7];
    const float* eg2  = (const float*)d_in[8];
    const float* ebt2 = (const float*)d_in[9];
    const float* eW3  = (const float*)d_in[10];
    const float* eb3  = (const float*)d_in[11];
    const float* eg3  = (const float*)d_in[12];
    const float* ebt3 = (const float*)d_in[13];
    const float* dW1  = (const float*)d_in[14];
    const float* db1  = (const float*)d_in[15];
    const float* dg1  = (const float*)d_in[16];
    const float* dbt1 = (const float*)d_in[17];
    const float* dW2  = (const float*)d_in[18];
    const float* db2  = (const float*)d_in[19];
    const float* dg2  = (const float*)d_in[20];
    const float* dbt2 = (const float*)d_in[21];
    const float* dW3  = (const float*)d_in[22];
    const float* db3  = (const float*)d_in[23];
    const float* dg3  = (const float*)d_in[24];
    const float* dbt3 = (const float*)d_in[25];
    float* out = (float*)d_out;

    float *a1, *a2, *a3, *q, *d1, *d2, *bnSc, *bnSh;
    cudaGetSymbolAddress((void**)&a1, g_a1);
    cudaGetSymbolAddress((void**)&a2, g_a2);
    cudaGetSymbolAddress((void**)&a3, g_a3);
    cudaGetSymbolAddress((void**)&q,  g_q);
    cudaGetSymbolAddress((void**)&d1, g_d1);
    cudaGetSymbolAddress((void**)&d2, g_d2);
    cudaGetSymbolAddress((void**)&bnSc, g_bnSc);
    cudaGetSymbolAddress((void**)&bnSh, g_bnSh);
    #define SLOT(i) (bnSc + (i) * 64), (bnSh + (i) * 64)

    // dynamic smem sizes for conv_mma
    const int PS = 34 * 36 + 1;
    const int smemC1 = (8 * PS + 128 * (2 * 8 + 8)) * 4;   // NT=2
    const int smemC  = (8 * PS + 128 * (4 * 8 + 8)) * 4;   // NT=4

    // ---------------- encoder (compensated TF32 mma) ----------------
    // conv1: 3->16, 256->128. 8x8 tiles x 64 = 4096 blocks, NT=2
    cudaFuncSetAttribute((const void*)conv_mma<3, 16, 2, 256, 256, false>,
                         cudaFuncAttributeMaxDynamicSharedMemorySize, smemC1);
    conv_mma<3, 16, 2, 256, 256, false><<<dim3(4096, 1), 256, smemC1>>>(
        x, eW1, eb1, a1, nullptr, nullptr);
    bn_stats<<<16 * 32, 256>>>(a1, 16, 128 * 128);
    bn_finalize<<<16, 32>>>(eg1, ebt1, 128 * 128, SLOT(0));

    // conv2: 16->32, 128->64. 4x4 tiles x 64 = 1024 blocks, NT=4
    cudaFuncSetAttribute((const void*)conv_mma<16, 32, 4, 128, 128, true>,
                         cudaFuncAttributeMaxDynamicSharedMemorySize, smemC);
    conv_mma<16, 32, 4, 128, 128, true><<<dim3(1024, 1), 256, smemC>>>(
        a1, eW2, eb2, a2, SLOT(0));
    bn_stats<<<32 * 32, 256>>>(a2, 32, 64 * 64);
    bn_finalize<<<32, 32>>>(eg2, ebt2, 64 * 64, SLOT(1));

    // conv3: 32->64, 64->32. 2x2 tiles x 64 = 256 blocks, 2 co-groups, NT=4
    cudaFuncSetAttribute((const void*)conv_mma<32, 64, 4, 64, 64, true>,
                         cudaFuncAttributeMaxDynamicSharedMemorySize, smemC);
    conv_mma<32, 64, 4, 64, 64, true><<<dim3(256, 2), 256, smemC>>>(
        a2, eW3, eb3, a3, SLOT(1));
    bn_stats<<<64 * 32, 256>>>(a3, 64, 32 * 32);
    bn_finalize<<<64, 32>>>(eg3, ebt3, 32 * 32, SLOT(2));

    // ---------------- vector quantization (exact fp32) ----------------
    code_norms<<<1, 512>>>(cb);
    vq_argmin<<<512, 128>>>(a3, cb, SLOT(2));
    vq_loss_final<<<1, 512>>>(out + (out_size - 1));
    vq_scatter<<<nblk((long long)BB * 64 * 32 * 32), 256>>>(q, cb);

    // ---------------- decoder (TF32 mma) ----------------
    deconv_mma<64, 32, 4, 8, 32, 32, false><<<512, 256>>>(
        q, dW1, db1, d1, nullptr, nullptr);
    bn_stats<<<32 * 32, 256>>>(d1, 32, 64 * 64);
    bn_finalize<<<32, 32>>>(dg1, dbt1, 64 * 64, SLOT(3));

    deconv_mma<32, 16, 2, 16, 64, 64, true><<<2048, 256>>>(
        d1, dW2, db2, d2, SLOT(3));
    bn_stats<<<16 * 32, 256>>>(d2, 16, 128 * 128);
    bn_finalize<<<16, 32>>>(dg2, dbt2, 128 * 128, SLOT(4));

    deconv_mma<16, 3, 1, 16, 128, 128, true><<<8192, 256>>>(
        d2, dW3, db3, out, SLOT(4));
    {
        const long long T = (long long)BB * 3 * 256 * 256;
        bn_stats<<<3 * 32, 256>>>(out, 3, 256 * 256);
        bn_finalize<<<3, 32>>>(dg3, dbt3, 256 * 256, SLOT(5));
        bn_apply_tanh<<<nblk(T / 4), 256>>>(out, 3, 256 * 256, (int)(T / 4), SLOT(5));
    }
    #undef SLOT
}

// round 12
// speedup vs baseline: 1.0665x; 1.0665x over previous
#include <cuda_runtime.h>
#include <math.h>

// ---------------------------------------------------------------------------
// VQ-VAE forward. Encoder: scalar fp32 (f32x2 FMA, smem tiles). Decoder: TF32
// mma (pre-converted operands); deconv1 gathers codebook directly (no scatter).
// BN fused into consumers; exact fp32 VQ argmin.
// ---------------------------------------------------------------------------

#define BB 64
static const float BN_EPS = 1e-5f;

// ------------------------- scratch (device globals) ------------------------
__device__ float g_a1[64 * 16 * 128 * 128];
__device__ float g_a2[64 * 32 * 64 * 64];
__device__ float g_a3[64 * 64 * 32 * 32];
__device__ float g_d1[64 * 32 * 64 * 64];
__device__ float g_d2[64 * 16 * 128 * 128];

__device__ int    g_idx[65536];
__device__ float  g_codeNorm[512];
__device__ float2 g_part[64 * 32];
__device__ float  g_bnSc[6 * 64];
__device__ float  g_bnSh[6 * 64];
__device__ float  g_lossPart[512];

// ---------------------------- f32x2 helpers --------------------------------
__device__ __forceinline__ unsigned long long splat2(float v) {
    unsigned long long r;
    asm("mov.b64 %0, {%1, %1};" : "=l"(r) : "r"(__float_as_uint(v)));
    return r;
}
__device__ __forceinline__ unsigned long long pack2(float a, float b) {
    unsigned long long r;
    asm("mov.b64 %0, {%1, %2};" : "=l"(r)
        : "r"(__float_as_uint(a)), "r"(__float_as_uint(b)));
    return r;
}
__device__ __forceinline__ void unpack2(unsigned long long p, float& a, float& b) {
    unsigned int lo, hi;
    asm("mov.b64 {%0, %1}, %2;" : "=r"(lo), "=r"(hi) : "l"(p));
    a = __uint_as_float(lo); b = __uint_as_float(hi);
}
__device__ __forceinline__ void fma2(unsigned long long& acc,
                                     unsigned long long a, unsigned long long b) {
    asm("fma.rn.f32x2 %0, %1, %2, %0;" : "+l"(acc) : "l"(a), "l"(b));
}

// ---------------------------- tf32 mma helpers -----------------------------
__device__ __forceinline__ unsigned int f2tf(float x) {
    unsigned int r;
    asm("cvt.rna.tf32.f32 %0, %1;" : "=r"(r) : "f"(x));
    return r;
}
__device__ __forceinline__ void mma_tf32(float* c, const unsigned int* a,
                                         const unsigned int* b) {
    asm volatile(
        "mma.sync.aligned.m16n8k8.row.col.f32.tf32.tf32.f32 "
        "{%0,%1,%2,%3}, {%4,%5,%6,%7}, {%8,%9}, {%0,%1,%2,%3};"
        : "+f"(c[0]), "+f"(c[1]), "+f"(c[2]), "+f"(c[3])
        : "r"(a[0]), "r"(a[1]), "r"(a[2]), "r"(a[3]), "r"(b[0]), "r"(b[1]));
}

// ------------------------------ conv k4 s2 p1 (scalar, encoder) ------------
// Block (128 thr) = 32x16 output tile; thread = 2x2 pixels x COUTG channels.
template <int CIN, int COUT, int COUTG, int CICHUNK, int HIN, int WIN, bool FUSE>
__global__ __launch_bounds__(128, 5)
void conv_q(const float* __restrict__ in, const float* __restrict__ w,
            const float* __restrict__ bias, float* __restrict__ out,
            const float* __restrict__ bnsc, const float* __restrict__ bnsh)
{
    constexpr int HOUT = HIN / 2, WOUT = WIN / 2;
    constexpr int NBX = WOUT / 32, NBY = HOUT / 16;
    constexpr int TR = 34, TC = 66, TP = 68;

    __shared__ __align__(16) float tile[CICHUNK][TR][TP];
    __shared__ __align__(16) float ws[CICHUNK * 16 * COUTG];

    const int b  = blockIdx.x;
    const int tx = b % NBX;
    const int ty = (b / NBX) % NBY;
    const int n  = b / (NBX * NBY);
    const int cog = blockIdx.y * COUTG;
    const int lx = threadIdx.x & 15, ly = threadIdx.x >> 4;

    const int X0 = tx * 64 - 1, Y0 = ty * 32 - 1;
    const float* inn = in + (long long)n * CIN * HIN * WIN;

    unsigned long long acc[4][COUTG / 2];
    #pragma unroll
    for (int j = 0; j < COUTG / 2; j++) {
        const unsigned long long bp =
            pack2(__ldg(&bias[cog + 2 * j]), __ldg(&bias[cog + 2 * j + 1]));
        acc[0][j] = bp; acc[1][j] = bp; acc[2][j] = bp; acc[3][j] = bp;
    }

    for (int ci0 = 0; ci0 < CIN; ci0 += CICHUNK) {
        __syncthreads();
        for (int t = threadIdx.x; t < COUTG * CICHUNK * 16; t += 128) {
            const int j  = t % COUTG;
            const int kk = t / COUTG;
            ws[t] = w[(cog + j) * CIN * 16 + ci0 * 16 + kk];
        }
        for (int t = threadIdx.x; t < CICHUNK * TR * TC; t += 128) {
            const int c  = t / (TR * TC);
            const int r  = (t / TC) % TR;
            const int cc = t % TC;
            const int gyy = Y0 + r, gxx = X0 + cc;
            const bool ok = ((unsigned)gyy < (unsigned)HIN) &&
                            ((unsigned)gxx < (unsigned)WIN);
            float v = ok ?
                __ldg(&inn[((long long)(ci0 + c) * HIN + gyy) * WIN + gxx]) : 0.f;
            if (FUSE && ok)
                v = fmaxf(0.f, fmaf(v, bnsc[ci0 + c], bnsh[ci0 + c]));
            tile[c][r][cc] = v;
        }
        __syncthreads();

        #pragma unroll
        for (int cil = 0; cil < CICHUNK; cil++) {
            #pragma unroll
            for (int ky = 0; ky < 4; ky++) {
                float ra[6], rb[6];
                {
                    const float4 a4 = *(const float4*)&tile[cil][4*ly+ky][4*lx];
                    const float2 a2 = *(const float2*)&tile[cil][4*ly+ky][4*lx+4];
                    ra[0]=a4.x; ra[1]=a4.y; ra[2]=a4.z; ra[3]=a4.w; ra[4]=a2.x; ra[5]=a2.y;
                    const float4 b4 = *(const float4*)&tile[cil][4*ly+2+ky][4*lx];
                    const float2 b2 = *(const float2*)&tile[cil][4*ly+2+ky][4*lx+4];
                    rb[0]=b4.x; rb[1]=b4.y; rb[2]=b4.z; rb[3]=b4.w; rb[4]=b2.x; rb[5]=b2.y;
                }
                #pragma unroll
                for (int kx = 0; kx < 4; kx++) {
                    const ulonglong2* w8 =
                        (const ulonglong2*)&ws[(cil * 16 + ky * 4 + kx) * COUTG];
                    ulonglong2 wv[COUTG / 4];
                    #pragma unroll
                    for (int q = 0; q < COUTG / 4; q++) wv[q] = w8[q];
                    #pragma unroll
                    for (int ix = 0; ix < 2; ix++) {
                        const unsigned long long tA = splat2(ra[2 * ix + kx]);
                        const unsigned long long tB = splat2(rb[2 * ix + kx]);
                        #pragma unroll
                        for (int q = 0; q < COUTG / 4; q++) {
                            fma2(acc[ix][2 * q + 0], tA, wv[q].x);
                            fma2(acc[ix][2 * q + 1], tA, wv[q].y);
                            fma2(acc[2 + ix][2 * q + 0], tB, wv[q].x);
                            fma2(acc[2 + ix][2 * q + 1], tB, wv[q].y);
                        }
                    }
                }
            }
        }
    }

    const int oy = ty * 16 + 2 * ly, ox = tx * 32 + 2 * lx;
    #pragma unroll
    for (int j = 0; j < COUTG; j++) {
        float v00, v01, v10, v11, tA, tB;
        unpack2(acc[0][j >> 1], tA, tB); v00 = (j & 1) ? tB : tA;
        unpack2(acc[1][j >> 1], tA, tB); v01 = (j & 1) ? tB : tA;
        unpack2(acc[2][j >> 1], tA, tB); v10 = (j & 1) ? tB : tA;
        unpack2(acc[3][j >> 1], tA, tB); v11 = (j & 1) ? tB : tA;
        const long long cb = (long long)n * COUT + cog + j;
        *(float2*)&out[(cb * HOUT + oy) * WOUT + ox]     = make_float2(v00, v01);
        *(float2*)&out[(cb * HOUT + oy + 1) * WOUT + ox] = make_float2(v10, v11);
    }
}

// --------------------- deconv k4 s2 p1 via TF32 mma ------------------------
// Operands pre-converted to tf32 at staging. GATHER: input gathered from
// codebook via g_idx (deconv1) instead of a dense tensor.
template <int CIN, int COUT, int NT, int KC, int HIN, int WIN, bool FUSE, bool GATHER>
__global__ __launch_bounds__(256)
void deconv_mma(const float* __restrict__ in, const float* __restrict__ w,
                const float* __restrict__ bias, float* __restrict__ out,
                const float* __restrict__ bnsc, const float* __restrict__ bnsh,
                const int* __restrict__ idxp)
{
    constexpr int COPAD = COUT + 8;
    constexpr int HOUT = 2 * HIN, WOUT = 2 * WIN;
    constexpr int NBX = WIN / 16, NBY = HIN / 8;

    __shared__ unsigned int tile[KC][10][20];
    __shared__ unsigned int wB[16 * KC * COPAD];
    __shared__ int codes[10 * 20];

    const int b  = blockIdx.x;
    const int tx = b % NBX;
    const int ty = (b / NBX) % NBY;
    const int n  = b / (NBX * NBY);
    const int X0 = tx * 16, Y0 = ty * 8;

    const int lane = threadIdx.x & 31;
    const int wid  = threadIdx.x >> 5;
    const int px = wid & 1, py = (wid >> 1) & 1, h = wid >> 2;

    const float* inn = in + (GATHER ? 0 : (long long)n * CIN * HIN * WIN);

    if (GATHER) {
        for (int t = threadIdx.x; t < 10 * 18; t += 256) {
            const int r = t / 18, cc = t % 18;
            const int gy = Y0 - 1 + r, gx = X0 - 1 + cc;
            const bool ok = ((unsigned)gy < (unsigned)HIN) &&
                            ((unsigned)gx < (unsigned)WIN);
            codes[r * 20 + cc] = ok ? idxp[n * (HIN * WIN) + gy * WIN + gx] : -1;
        }
    }

    float acc[4][NT][4];
    #pragma unroll
    for (int nt = 0; nt < NT; nt++) {
        const int co0 = nt * 8 + 2 * (lane & 3);
        const float b0 = (co0     < COUT) ? __ldg(&bias[co0])     : 0.f;
        const float b1 = (co0 + 1 < COUT) ? __ldg(&bias[co0 + 1]) : 0.f;
        #pragma unroll
        for (int mt = 0; mt < 4; mt++) {
            acc[mt][nt][0] = b0; acc[mt][nt][1] = b1;
            acc[mt][nt][2] = b0; acc[mt][nt][3] = b1;
        }
    }

    for (int ci0 = 0; ci0 < CIN; ci0 += KC) {
        __syncthreads();
        for (int t = threadIdx.x; t < 16 * KC * COPAD; t += 256) {
            const int co  = t % COPAD;
            const int rem = t / COPAD;
            const int ci  = rem % KC;
            const int tap = rem / KC;
            const float v = (co < COUT) ?
                __ldg(&w[(co * CIN + ci0 + ci) * 16 + tap]) : 0.f;
            wB[t] = f2tf(v);
        }
        for (int t = threadIdx.x; t < KC * 10 * 18; t += 256) {
            const int cc  = t % 18;
            const int rem = t / 18;
            const int r   = rem % 10;
            const int c   = rem / 10;
            float v = 0.f;
            if (GATHER) {
                const int code = codes[r * 20 + cc];
                if (code >= 0) v = __ldg(&in[code * 64 + ci0 + c]);
            } else {
                const int gy = Y0 - 1 + r, gx = X0 - 1 + cc;
                const bool ok = ((unsigned)gy < (unsigned)HIN) &&
                                ((unsigned)gx < (unsigned)WIN);
                if (ok) {
                    v = __ldg(&inn[((long long)(ci0 + c) * HIN + gy) * WIN + gx]);
                    if (FUSE)
                        v = fmaxf(0.f, fmaf(v, bnsc[ci0 + c], bnsh[ci0 + c]));
                }
            }
            tile[c][r][cc] = f2tf(v);
        }
        __syncthreads();

        #pragma unroll
        for (int a = 0; a < 2; a++) {
            #pragma unroll
            for (int bs = 0; bs < 2; bs++) {
                const int tap = (py + 2 * a) * 4 + (px + 2 * bs);
                const unsigned int* wT = &wB[tap * KC * COPAD];
                const int xA = (lane >> 2) + px + bs;
                #pragma unroll
                for (int kk = 0; kk < KC / 8; kk++) {
                    const int kA = kk * 8 + (lane & 3);
                    unsigned int A[4][4];
                    #pragma unroll
                    for (int mt = 0; mt < 4; mt++) {
                        const int yA = h * 4 + mt + py + a;
                        A[mt][0] = tile[kA][yA][xA];
                        A[mt][1] = tile[kA][yA][xA + 8];
                        A[mt][2] = tile[kA + 4][yA][xA];
                        A[mt][3] = tile[kA + 4][yA][xA + 8];
                    }
                    #pragma unroll
                    for (int nt = 0; nt < NT; nt++) {
                        unsigned int Bf[2];
                        const int coL = nt * 8 + (lane >> 2);
                        Bf[0] = wT[kA * COPAD + coL];
                        Bf[1] = wT[(kA + 4) * COPAD + coL];
                        #pragma unroll
                        for (int mt = 0; mt < 4; mt++)
                            mma_tf32(acc[mt][nt], A[mt], Bf);
                    }
                }
            }
        }
    }

    #pragma unroll
    for (int mt = 0; mt < 4; mt++) {
        const int orow = 2 * (Y0 + h * 4 + mt) + py;
        const int qx0 = lane >> 2;
        const int ox0 = 2 * (X0 + qx0) + px;
        const int ox1 = 2 * (X0 + qx0 + 8) + px;
        #pragma unroll
        for (int nt = 0; nt < NT; nt++) {
            const int co0 = nt * 8 + 2 * (lane & 3);
            if (co0 < COUT) {
                float* rowp = out + (((long long)n * COUT + co0) * HOUT + orow) * WOUT;
                rowp[ox0] = acc[mt][nt][0];
                rowp[ox1] = acc[mt][nt][2];
            }
            if (co0 + 1 < COUT) {
                float* rowp = out + (((long long)n * COUT + co0 + 1) * HOUT + orow) * WOUT;
                rowp[ox0] = acc[mt][nt][1];
                rowp[ox1] = acc[mt][nt][3];
            }
        }
    }
}

// ------------------------------- batchnorm ---------------------------------
__global__ __launch_bounds__(256)
void bn_stats(const float* __restrict__ x, int C, int HW)
{
    const int c = blockIdx.x >> 5;
    const int s = blockIdx.x & 31;
    const int chunk4 = HW >> 7;

    float sum = 0.f, sq = 0.f;
    for (int n = 0; n < BB; n++) {
        const float4* base = (const float4*)(x + ((long long)(n * C + c)) * HW) +
                             s * chunk4;
        for (int p = threadIdx.x; p < chunk4; p += 256) {
            float4 v = base[p];
            sum += v.x + v.y + v.z + v.w;
            sq = fmaf(v.x, v.x, sq); sq = fmaf(v.y, v.y, sq);
            sq = fmaf(v.z, v.z, sq); sq = fmaf(v.w, v.w, sq);
        }
    }
    __shared__ float s1[256], s2[256];
    s1[threadIdx.x] = sum; s2[threadIdx.x] = sq;
    __syncthreads();
    for (int off = 128; off; off >>= 1) {
        if (threadIdx.x < off) {
            s1[threadIdx.x] += s1[threadIdx.x + off];
            s2[threadIdx.x] += s2[threadIdx.x + off];
        }
        __syncthreads();
    }
    if (threadIdx.x == 0) g_part[blockIdx.x] = make_float2(s1[0], s2[0]);
}

__global__ void bn_finalize(const float* __restrict__ gam,
                            const float* __restrict__ bet, int HW,
                            float* __restrict__ outSc, float* __restrict__ outSh)
{
    const int c = blockIdx.x;
    float2 p = g_part[c * 32 + threadIdx.x];
    double S = p.x, Q = p.y;
    for (int off = 16; off; off >>= 1) {
        S += __shfl_down_sync(0xffffffffu, S, off);
        Q += __shfl_down_sync(0xffffffffu, Q, off);
    }
    if (threadIdx.x == 0) {
        const double P = (double)BB * (double)HW;
        const double mean = S / P;
        const double var  = Q / P - mean * mean;
        const float rstd  = (float)(1.0 / sqrt(var + (double)BN_EPS));
        const float sc = gam[c] * rstd;
        outSc[c] = sc;
        outSh[c] = bet[c] - (float)mean * sc;
    }
}

__global__ __launch_bounds__(256)
void bn_apply_tanh(float* __restrict__ x, int C, int HW, int total4,
                   const float* __restrict__ sc_, const float* __restrict__ sh_)
{
    const int i = blockIdx.x * 256 + threadIdx.x;
    if (i >= total4) return;
    const int hw4 = HW >> 2;
    const int c = (i / hw4) % C;
    const float sc = sc_[c], sh = sh_[c];
    float4 v = ((float4*)x)[i];
    v.x = tanhf(fmaf(v.x, sc, sh)); v.y = tanhf(fmaf(v.y, sc, sh));
    v.z = tanhf(fmaf(v.z, sc, sh)); v.w = tanhf(fmaf(v.w, sc, sh));
    ((float4*)x)[i] = v;
}

// ---------------------------------- VQ -------------------------------------
__global__ void code_norms(const float* __restrict__ cb)
{
    const int k = threadIdx.x;
    float s = 0.f;
    const float* r = cb + k * 64;
    #pragma unroll
    for (int d = 0; d < 64; d++) s = fmaf(r[d], r[d], s);
    g_codeNorm[k] = s;
}

__global__ __launch_bounds__(128)
void vq_argmin(const float* __restrict__ ze, const float* __restrict__ cb,
               const float* __restrict__ sc_, const float* __restrict__ sh_)
{
    __shared__ float sc[64 * 64];
    __shared__ float scn[64];
    __shared__ float red[128];
    __shared__ float ssc[64], ssh[64];

    if (threadIdx.x < 64) {
        ssc[threadIdx.x] = sc_[threadIdx.x];
        ssh[threadIdx.x] = sh_[threadIdx.x];
    }
    __syncthreads();

    const int idx = blockIdx.x * 128 + threadIdx.x;
    const int n  = idx >> 10;
    const int hw = idx & 1023;
    const float* base = ze + (long long)n * 64 * 1024 + hw;

    float z[64];
    #pragma unroll
    for (int d = 0; d < 64; d++)
        z[d] = fmaxf(0.f, fmaf(base[d * 1024], ssc[d], ssh[d]));
    float zz = 0.f;
    #pragma unroll
    for (int d = 0; d < 64; d++) zz = fmaf(z[d], z[d], zz);

    float best = 3.4e38f;
    int   bi   = 0;
    for (int ch = 0; ch < 8; ch++) {
        __syncthreads();
        for (int t = threadIdx.x; t < 1024; t += 128)
            ((float4*)sc)[t] = ((const float4*)(cb + ch * 4096))[t];
        if (threadIdx.x < 64) scn[threadIdx.x] = g_codeNorm[ch * 64 + threadIdx.x];
        __syncthreads();
        #pragma unroll 2
        for (int j = 0; j < 64; j++) {
            const float4* cp = (const float4*)&sc[j * 64];
            float dot = 0.f;
            #pragma unroll
            for (int d4 = 0; d4 < 16; d4++) {
                float4 c4 = cp[d4];
                dot = fmaf(z[4*d4+0], c4.x, dot);
                dot = fmaf(z[4*d4+1], c4.y, dot);
                dot = fmaf(z[4*d4+2], c4.z, dot);
                dot = fmaf(z[4*d4+3], c4.w, dot);
            }
            const float dist = zz - 2.f * dot + scn[j];
            const int k = ch * 64 + j;
            if (dist < best) { best = dist; bi = k; }
        }
    }
    g_idx[idx] = bi;

    const float* cr = cb + bi * 64;
    float e = 0.f;
    #pragma unroll
    for (int d = 0; d < 64; d++) { float df = z[d] - cr[d]; e = fmaf(df, df, e); }

    red[threadIdx.x] = e;
    __syncthreads();
    for (int off = 64; off; off >>= 1) {
        if (threadIdx.x < off) red[threadIdx.x] += red[threadIdx.x + off];
        __syncthreads();
    }
    if (threadIdx.x == 0) g_lossPart[blockIdx.x] = red[0];
}

__global__ void vq_loss_final(float* __restrict__ loss_out)
{
    __shared__ double red[512];
    red[threadIdx.x] = (double)g_lossPart[threadIdx.x];
    __syncthreads();
    for (int off = 256; off; off >>= 1) {
        if (threadIdx.x < off) red[threadIdx.x] += red[threadIdx.x + off];
        __syncthreads();
    }
    if (threadIdx.x == 0)
        loss_out[0] = (float)(2.0 * red[0] / (65536.0 * 64.0));
}

// -------------------------------- launch -----------------------------------
static inline int nblk(long long total) { return (int)((total + 255) / 256); }

extern "C" void kernel_launch(void* const* d_in, const int* in_sizes, int n_in,
                              void* d_out, int out_size)
{
    (void)in_sizes; (void)n_in;
    const float* x    = (const float*)d_in[0];
    const float* cb   = (const float*)d_in[1];
    const float* eW1  = (const float*)d_in[2];
    const float* eb1  = (const float*)d_in[3];
    const float* eg1  = (const float*)d_in[4];
    const float* ebt1 = (const float*)d_in[5];
    const float* eW2  = (const float*)d_in[6];
    const float* eb2  = (const float*)d_in[7];
    const float* eg2  = (const float*)d_in[8];
    const float* ebt2 = (const float*)d_in[9];
    const float* eW3  = (const float*)d_in[10];
    const float* eb3  = (const float*)d_in[11];
    const float* eg3  = (const float*)d_in[12];
    const float* ebt3 = (const float*)d_in[13];
    const float* dW1  = (const float*)d_in[14];
    const float* db1  = (const float*)d_in[15];
    const float* dg1  = (const float*)d_in[16];
    const float* dbt1 = (const float*)d_in[17];
    const float* dW2  = (const float*)d_in[18];
    const float* db2  = (const float*)d_in[19];
    const float* dg2  = (const float*)d_in[20];
    const float* dbt2 = (const float*)d_in[21];
    const float* dW3  = (const float*)d_in[22];
    const float* db3  = (const float*)d_in[23];
    const float* dg3  = (const float*)d_in[24];
    const float* dbt3 = (const float*)d_in[25];
    float* out = (float*)d_out;

    float *a1, *a2, *a3, *d1, *d2, *bnSc, *bnSh;
    int* idxp;
    cudaGetSymbolAddress((void**)&a1, g_a1);
    cudaGetSymbolAddress((void**)&a2, g_a2);
    cudaGetSymbolAddress((void**)&a3, g_a3);
    cudaGetSymbolAddress((void**)&d1, g_d1);
    cudaGetSymbolAddress((void**)&d2, g_d2);
    cudaGetSymbolAddress((void**)&bnSc, g_bnSc);
    cudaGetSymbolAddress((void**)&bnSh, g_bnSh);
    cudaGetSymbolAddress((void**)&idxp, g_idx);
    #define SLOT(i) (bnSc + (i) * 64), (bnSh + (i) * 64)

    // ---------------- encoder (scalar fp32) ----------------
    conv_q<3, 16, 16, 1, 256, 256, false><<<dim3(2048, 1), 128>>>(
        x, eW1, eb1, a1, nullptr, nullptr);
    bn_stats<<<16 * 32, 256>>>(a1, 16, 128 * 128);
    bn_finalize<<<16, 32>>>(eg1, ebt1, 128 * 128, SLOT(0));

    conv_q<16, 32, 16, 2, 128, 128, true><<<dim3(512, 2), 128>>>(
        a1, eW2, eb2, a2, SLOT(0));
    bn_stats<<<32 * 32, 256>>>(a2, 32, 64 * 64);
    bn_finalize<<<32, 32>>>(eg2, ebt2, 64 * 64, SLOT(1));

    conv_q<32, 64, 16, 2, 64, 64, true><<<dim3(128, 4), 128>>>(
        a2, eW3, eb3, a3, SLOT(1));
    bn_stats<<<64 * 32, 256>>>(a3, 64, 32 * 32);
    bn_finalize<<<64, 32>>>(eg3, ebt3, 32 * 32, SLOT(2));

    // ---------------- vector quantization (exact fp32) ----------------
    code_norms<<<1, 512>>>(cb);
    vq_argmin<<<512, 128>>>(a3, cb, SLOT(2));
    vq_loss_final<<<1, 512>>>(out + (out_size - 1));

    // ---------------- decoder (TF32 mma) ----------------
    // deconv1: gathers codebook directly via g_idx (no scatter kernel)
    deconv_mma<64, 32, 4, 8, 32, 32, false, true><<<512, 256>>>(
        cb, dW1, db1, d1, nullptr, nullptr, idxp);
    bn_stats<<<32 * 32, 256>>>(d1, 32, 64 * 64);
    bn_finalize<<<32, 32>>>(dg1, dbt1, 64 * 64, SLOT(3));

    deconv_mma<32, 16, 2, 16, 64, 64, true, false><<<2048, 256>>>(
        d1, dW2, db2, d2, SLOT(3), nullptr);
    bn_stats<<<16 * 32, 256>>>(d2, 16, 128 * 128);
    bn_finalize<<<16, 32>>>(dg2, dbt2, 128 * 128, SLOT(4));

    deconv_mma<16, 3, 1, 16, 128, 128, true, false><<<8192, 256>>>(
        d2, dW3, db3, out, SLOT(4), nullptr);
    {
        const long long T = (long long)BB * 3 * 256 * 256;
        bn_stats<<<3 * 32, 256>>>(out, 3, 256 * 256);
        bn_finalize<<<3, 32>>>(dg3, dbt3, 256 * 256, SLOT(5));
        bn_apply_tanh<<<nblk(T / 4), 256>>>(out, 3, 256 * 256, (int)(T / 4), SLOT(5));
    }
    #undef SLOT
}

// round 14
// speedup vs baseline: 1.1540x; 1.0821x over previous
#include <cuda_runtime.h>
#include <math.h>

// ---------------------------------------------------------------------------
// VQ-VAE forward. Encoder: scalar fp32 (bit-exact BN stats path — argmin-safe).
// Decoder: TF32 mma with FUSED BN statistics in epilogues; deconv1 gathers
// codebook directly. Exact fp32 VQ argmin.
// ---------------------------------------------------------------------------

#define BB 64
#define MAXB 8192
static const float BN_EPS = 1e-5f;

// ------------------------- scratch (device globals) ------------------------
__device__ float g_a1[64 * 16 * 128 * 128];
__device__ float g_a2[64 * 32 * 64 * 64];
__device__ float g_a3[64 * 64 * 32 * 32];
__device__ float g_d1[64 * 32 * 64 * 64];
__device__ float g_d2[64 * 16 * 128 * 128];

__device__ int    g_idx[65536];
__device__ float  g_codeNorm[512];
__device__ float2 g_part[64 * 32];        // encoder slab partials (bit-exact)
__device__ float2 g_stats[64 * MAXB];     // decoder per-block partials
__device__ float  g_bnSc[6 * 64];
__device__ float  g_bnSh[6 * 64];
__device__ float  g_lossPart[512];

// ---------------------------- f32x2 helpers --------------------------------
__device__ __forceinline__ unsigned long long splat2(float v) {
    unsigned long long r;
    asm("mov.b64 %0, {%1, %1};" : "=l"(r) : "r"(__float_as_uint(v)));
    return r;
}
__device__ __forceinline__ unsigned long long pack2(float a, float b) {
    unsigned long long r;
    asm("mov.b64 %0, {%1, %2};" : "=l"(r)
        : "r"(__float_as_uint(a)), "r"(__float_as_uint(b)));
    return r;
}
__device__ __forceinline__ void unpack2(unsigned long long p, float& a, float& b) {
    unsigned int lo, hi;
    asm("mov.b64 {%0, %1}, %2;" : "=r"(lo), "=r"(hi) : "l"(p));
    a = __uint_as_float(lo); b = __uint_as_float(hi);
}
__device__ __forceinline__ void fma2(unsigned long long& acc,
                                     unsigned long long a, unsigned long long b) {
    asm("fma.rn.f32x2 %0, %1, %2, %0;" : "+l"(acc) : "l"(a), "l"(b));
}

// ---------------------------- tf32 mma helpers -----------------------------
__device__ __forceinline__ unsigned int f2tf(float x) {
    unsigned int r;
    asm("cvt.rna.tf32.f32 %0, %1;" : "=r"(r) : "f"(x));
    return r;
}
__device__ __forceinline__ void mma_tf32(float* c, const unsigned int* a,
                                         const unsigned int* b) {
    asm volatile(
        "mma.sync.aligned.m16n8k8.row.col.f32.tf32.tf32.f32 "
        "{%0,%1,%2,%3}, {%4,%5,%6,%7}, {%8,%9}, {%0,%1,%2,%3};"
        : "+f"(c[0]), "+f"(c[1]), "+f"(c[2]), "+f"(c[3])
        : "r"(a[0]), "r"(a[1]), "r"(a[2]), "r"(a[3]), "r"(b[0]), "r"(b[1]));
}

// ------------------------------ conv k4 s2 p1 (scalar, encoder) ------------
// Block (128 thr) = 32x16 output tile; thread = 2x2 pixels x COUTG channels.
template <int CIN, int COUT, int COUTG, int CICHUNK, int HIN, int WIN, bool FUSE>
__global__ __launch_bounds__(128, 5)
void conv_q(const float* __restrict__ in, const float* __restrict__ w,
            const float* __restrict__ bias, float* __restrict__ out,
            const float* __restrict__ bnsc, const float* __restrict__ bnsh)
{
    constexpr int HOUT = HIN / 2, WOUT = WIN / 2;
    constexpr int NBX = WOUT / 32, NBY = HOUT / 16;
    constexpr int TR = 34, TC = 66, TP = 68;

    __shared__ __align__(16) float tile[CICHUNK][TR][TP];
    __shared__ __align__(16) float ws[CICHUNK * 16 * COUTG];

    const int b  = blockIdx.x;
    const int tx = b % NBX;
    const int ty = (b / NBX) % NBY;
    const int n  = b / (NBX * NBY);
    const int cog = blockIdx.y * COUTG;
    const int lx = threadIdx.x & 15, ly = threadIdx.x >> 4;

    const int X0 = tx * 64 - 1, Y0 = ty * 32 - 1;
    const float* inn = in + (long long)n * CIN * HIN * WIN;

    unsigned long long acc[4][COUTG / 2];
    #pragma unroll
    for (int j = 0; j < COUTG / 2; j++) {
        const unsigned long long bp =
            pack2(__ldg(&bias[cog + 2 * j]), __ldg(&bias[cog + 2 * j + 1]));
        acc[0][j] = bp; acc[1][j] = bp; acc[2][j] = bp; acc[3][j] = bp;
    }

    for (int ci0 = 0; ci0 < CIN; ci0 += CICHUNK) {
        __syncthreads();
        for (int t = threadIdx.x; t < COUTG * CICHUNK * 16; t += 128) {
            const int j  = t % COUTG;
            const int kk = t / COUTG;
            ws[t] = w[(cog + j) * CIN * 16 + ci0 * 16 + kk];
        }
        for (int t = threadIdx.x; t < CICHUNK * TR * TC; t += 128) {
            const int c  = t / (TR * TC);
            const int r  = (t / TC) % TR;
            const int cc = t % TC;
            const int gyy = Y0 + r, gxx = X0 + cc;
            const bool ok = ((unsigned)gyy < (unsigned)HIN) &&
                            ((unsigned)gxx < (unsigned)WIN);
            float v = ok ?
                __ldg(&inn[((long long)(ci0 + c) * HIN + gyy) * WIN + gxx]) : 0.f;
            if (FUSE && ok)
                v = fmaxf(0.f, fmaf(v, bnsc[ci0 + c], bnsh[ci0 + c]));
            tile[c][r][cc] = v;
        }
        __syncthreads();

        #pragma unroll
        for (int cil = 0; cil < CICHUNK; cil++) {
            #pragma unroll
            for (int ky = 0; ky < 4; ky++) {
                float ra[6], rb[6];
                {
                    const float4 a4 = *(const float4*)&tile[cil][4*ly+ky][4*lx];
                    const float2 a2 = *(const float2*)&tile[cil][4*ly+ky][4*lx+4];
                    ra[0]=a4.x; ra[1]=a4.y; ra[2]=a4.z; ra[3]=a4.w; ra[4]=a2.x; ra[5]=a2.y;
                    const float4 b4 = *(const float4*)&tile[cil][4*ly+2+ky][4*lx];
                    const float2 b2 = *(const float2*)&tile[cil][4*ly+2+ky][4*lx+4];
                    rb[0]=b4.x; rb[1]=b4.y; rb[2]=b4.z; rb[3]=b4.w; rb[4]=b2.x; rb[5]=b2.y;
                }
                #pragma unroll
                for (int kx = 0; kx < 4; kx++) {
                    const ulonglong2* w8 =
                        (const ulonglong2*)&ws[(cil * 16 + ky * 4 + kx) * COUTG];
                    ulonglong2 wv[COUTG / 4];
                    #pragma unroll
                    for (int q = 0; q < COUTG / 4; q++) wv[q] = w8[q];
                    #pragma unroll
                    for (int ix = 0; ix < 2; ix++) {
                        const unsigned long long tA = splat2(ra[2 * ix + kx]);
                        const unsigned long long tB = splat2(rb[2 * ix + kx]);
                        #pragma unroll
                        for (int q = 0; q < COUTG / 4; q++) {
                            fma2(acc[ix][2 * q + 0], tA, wv[q].x);
                            fma2(acc[ix][2 * q + 1], tA, wv[q].y);
                            fma2(acc[2 + ix][2 * q + 0], tB, wv[q].x);
                            fma2(acc[2 + ix][2 * q + 1], tB, wv[q].y);
                        }
                    }
                }
            }
        }
    }

    const int oy = ty * 16 + 2 * ly, ox = tx * 32 + 2 * lx;
    #pragma unroll
    for (int j = 0; j < COUTG; j++) {
        float v00, v01, v10, v11, tA, tB;
        unpack2(acc[0][j >> 1], tA, tB); v00 = (j & 1) ? tB : tA;
        unpack2(acc[1][j >> 1], tA, tB); v01 = (j & 1) ? tB : tA;
        unpack2(acc[2][j >> 1], tA, tB); v10 = (j & 1) ? tB : tA;
        unpack2(acc[3][j >> 1], tA, tB); v11 = (j & 1) ? tB : tA;
        const long long cb = (long long)n * COUT + cog + j;
        *(float2*)&out[(cb * HOUT + oy) * WOUT + ox]     = make_float2(v00, v01);
        *(float2*)&out[(cb * HOUT + oy + 1) * WOUT + ox] = make_float2(v10, v11);
    }
}

// --------------------- deconv k4 s2 p1 via TF32 mma ------------------------
// Operands pre-converted to tf32 at staging. GATHER: input from codebook via
// g_idx. Epilogue: fused per-channel block partial stats -> g_stats.
template <int CIN, int COUT, int NT, int KC, int HIN, int WIN, bool FUSE, bool GATHER>
__global__ __launch_bounds__(256)
void deconv_mma(const float* __restrict__ in, const float* __restrict__ w,
                const float* __restrict__ bias, float* __restrict__ out,
                const float* __restrict__ bnsc, const float* __restrict__ bnsh,
                const int* __restrict__ idxp)
{
    constexpr int COPAD = COUT + 8;
    constexpr int HOUT = 2 * HIN, WOUT = 2 * WIN;
    constexpr int NBX = WIN / 16, NBY = HIN / 8;

    __shared__ unsigned int tile[KC][10][20];
    __shared__ unsigned int wB[16 * KC * COPAD];
    __shared__ int codes[10 * 20];
    __shared__ float sred[8][4][4][4];     // [wid][nt][l][s0,q0,s1,q1]

    const int b  = blockIdx.x;
    const int tx = b % NBX;
    const int ty = (b / NBX) % NBY;
    const int n  = b / (NBX * NBY);
    const int X0 = tx * 16, Y0 = ty * 8;

    const int lane = threadIdx.x & 31;
    const int wid  = threadIdx.x >> 5;
    const int px = wid & 1, py = (wid >> 1) & 1, h = wid >> 2;

    const float* inn = in + (GATHER ? 0 : (long long)n * CIN * HIN * WIN);

    if (GATHER) {
        for (int t = threadIdx.x; t < 10 * 18; t += 256) {
            const int r = t / 18, cc = t % 18;
            const int gy = Y0 - 1 + r, gx = X0 - 1 + cc;
            const bool ok = ((unsigned)gy < (unsigned)HIN) &&
                            ((unsigned)gx < (unsigned)WIN);
            codes[r * 20 + cc] = ok ? idxp[n * (HIN * WIN) + gy * WIN + gx] : -1;
        }
    }

    float acc[4][NT][4];
    #pragma unroll
    for (int nt = 0; nt < NT; nt++) {
        const int co0 = nt * 8 + 2 * (lane & 3);
        const float b0 = (co0     < COUT) ? __ldg(&bias[co0])     : 0.f;
        const float b1 = (co0 + 1 < COUT) ? __ldg(&bias[co0 + 1]) : 0.f;
        #pragma unroll
        for (int mt = 0; mt < 4; mt++) {
            acc[mt][nt][0] = b0; acc[mt][nt][1] = b1;
            acc[mt][nt][2] = b0; acc[mt][nt][3] = b1;
        }
    }

    for (int ci0 = 0; ci0 < CIN; ci0 += KC) {
        __syncthreads();
        for (int t = threadIdx.x; t < 16 * KC * COPAD; t += 256) {
            const int co  = t % COPAD;
            const int rem = t / COPAD;
            const int ci  = rem % KC;
            const int tap = rem / KC;
            const float v = (co < COUT) ?
                __ldg(&w[(co * CIN + ci0 + ci) * 16 + tap]) : 0.f;
            wB[t] = f2tf(v);
        }
        for (int t = threadIdx.x; t < KC * 10 * 18; t += 256) {
            const int cc  = t % 18;
            const int rem = t / 18;
            const int r   = rem % 10;
            const int c   = rem / 10;
            float v = 0.f;
            if (GATHER) {
                const int code = codes[r * 20 + cc];
                if (code >= 0) v = __ldg(&in[code * 64 + ci0 + c]);
            } else {
                const int gy = Y0 - 1 + r, gx = X0 - 1 + cc;
                const bool ok = ((unsigned)gy < (unsigned)HIN) &&
                                ((unsigned)gx < (unsigned)WIN);
                if (ok) {
                    v = __ldg(&inn[((long long)(ci0 + c) * HIN + gy) * WIN + gx]);
                    if (FUSE)
                        v = fmaxf(0.f, fmaf(v, bnsc[ci0 + c], bnsh[ci0 + c]));
                }
            }
            tile[c][r][cc] = f2tf(v);
        }
        __syncthreads();

        #pragma unroll
        for (int a = 0; a < 2; a++) {
            #pragma unroll
            for (int bs = 0; bs < 2; bs++) {
                const int tap = (py + 2 * a) * 4 + (px + 2 * bs);
                const unsigned int* wT = &wB[tap * KC * COPAD];
                const int xA = (lane >> 2) + px + bs;
                #pragma unroll
                for (int kk = 0; kk < KC / 8; kk++) {
                    const int kA = kk * 8 + (lane & 3);
                    unsigned int A[4][4];
                    #pragma unroll
                    for (int mt = 0; mt < 4; mt++) {
                        const int yA = h * 4 + mt + py + a;
                        A[mt][0] = tile[kA][yA][xA];
                        A[mt][1] = tile[kA][yA][xA + 8];
                        A[mt][2] = tile[kA + 4][yA][xA];
                        A[mt][3] = tile[kA + 4][yA][xA + 8];
                    }
                    #pragma unroll
                    for (int nt = 0; nt < NT; nt++) {
                        unsigned int Bf[2];
                        const int coL = nt * 8 + (lane >> 2);
                        Bf[0] = wT[kA * COPAD + coL];
                        Bf[1] = wT[(kA + 4) * COPAD + coL];
                        #pragma unroll
                        for (int mt = 0; mt < 4; mt++)
                            mma_tf32(acc[mt][nt], A[mt], Bf);
                    }
                }
            }
        }
    }

    #pragma unroll
    for (int mt = 0; mt < 4; mt++) {
        const int orow = 2 * (Y0 + h * 4 + mt) + py;
        const int qx0 = lane >> 2;
        const int ox0 = 2 * (X0 + qx0) + px;
        const int ox1 = 2 * (X0 + qx0 + 8) + px;
        #pragma unroll
        for (int nt = 0; nt < NT; nt++) {
            const int co0 = nt * 8 + 2 * (lane & 3);
            if (co0 < COUT) {
                float* rowp = out + (((long long)n * COUT + co0) * HOUT + orow) * WOUT;
                rowp[ox0] = acc[mt][nt][0];
                rowp[ox1] = acc[mt][nt][2];
            }
            if (co0 + 1 < COUT) {
                float* rowp = out + (((long long)n * COUT + co0 + 1) * HOUT + orow) * WOUT;
                rowp[ox0] = acc[mt][nt][1];
                rowp[ox1] = acc[mt][nt][3];
            }
        }
    }

    // ---- fused BN statistics (deterministic; decoder only) ----
    {
        const int l = lane & 3;
        #pragma unroll
        for (int nt = 0; nt < NT; nt++) {
            float s0 = 0.f, q0 = 0.f, s1 = 0.f, q1 = 0.f;
            #pragma unroll
            for (int mt = 0; mt < 4; mt++) {
                const float a0 = acc[mt][nt][0], a2 = acc[mt][nt][2];
                const float a1 = acc[mt][nt][1], a3 = acc[mt][nt][3];
                s0 += a0 + a2; q0 += a0 * a0 + a2 * a2;
                s1 += a1 + a3; q1 += a1 * a1 + a3 * a3;
            }
            #pragma unroll
            for (int off = 4; off < 32; off <<= 1) {
                s0 += __shfl_xor_sync(0xffffffffu, s0, off);
                q0 += __shfl_xor_sync(0xffffffffu, q0, off);
                s1 += __shfl_xor_sync(0xffffffffu, s1, off);
                q1 += __shfl_xor_sync(0xffffffffu, q1, off);
            }
            if ((lane >> 2) == 0) {
                sred[wid][nt][l][0] = s0; sred[wid][nt][l][1] = q0;
                sred[wid][nt][l][2] = s1; sred[wid][nt][l][3] = q1;
            }
        }
        __syncthreads();
        if (threadIdx.x < 4 * NT) {
            const int nt = threadIdx.x >> 2, l2 = threadIdx.x & 3;
            float s0 = 0.f, q0 = 0.f, s1 = 0.f, q1 = 0.f;
            #pragma unroll
            for (int w2 = 0; w2 < 8; w2++) {
                s0 += sred[w2][nt][l2][0]; q0 += sred[w2][nt][l2][1];
                s1 += sred[w2][nt][l2][2]; q1 += sred[w2][nt][l2][3];
            }
            const int ch0 = nt * 8 + 2 * l2;
            if (ch0 < COUT)     g_stats[ch0 * MAXB + blockIdx.x] = make_float2(s0, q0);
            if (ch0 + 1 < COUT) g_stats[(ch0 + 1) * MAXB + blockIdx.x] = make_float2(s1, q1);
        }
    }
}

// ------------------------------- batchnorm ---------------------------------
// Encoder path: bit-exact slab partials (unchanged since R2 — argmin-safe).
__global__ __launch_bounds__(256)
void bn_stats(const float* __restrict__ x, int C, int HW)
{
    const int c = blockIdx.x >> 5;
    const int s = blockIdx.x & 31;
    const int chunk4 = HW >> 7;

    float sum = 0.f, sq = 0.f;
    for (int n = 0; n < BB; n++) {
        const float4* base = (const float4*)(x + ((long long)(n * C + c)) * HW) +
                             s * chunk4;
        for (int p = threadIdx.x; p < chunk4; p += 256) {
            float4 v = base[p];
            sum += v.x + v.y + v.z + v.w;
            sq = fmaf(v.x, v.x, sq); sq = fmaf(v.y, v.y, sq);
            sq = fmaf(v.z, v.z, sq); sq = fmaf(v.w, v.w, sq);
        }
    }
    __shared__ float s1[256], s2[256];
    s1[threadIdx.x] = sum; s2[threadIdx.x] = sq;
    __syncthreads();
    for (int off = 128; off; off >>= 1) {
        if (threadIdx.x < off) {
            s1[threadIdx.x] += s1[threadIdx.x + off];
            s2[threadIdx.x] += s2[threadIdx.x + off];
        }
        __syncthreads();
    }
    if (threadIdx.x == 0) g_part[blockIdx.x] = make_float2(s1[0], s2[0]);
}

__global__ void bn_finalize(const float* __restrict__ gam,
                            const float* __restrict__ bet, int HW,
                            float* __restrict__ outSc, float* __restrict__ outSh)
{
    const int c = blockIdx.x;
    float2 p = g_part[c * 32 + threadIdx.x];
    double S = p.x, Q = p.y;
    for (int off = 16; off; off >>= 1) {
        S += __shfl_down_sync(0xffffffffu, S, off);
        Q += __shfl_down_sync(0xffffffffu, Q, off);
    }
    if (threadIdx.x == 0) {
        const double P = (double)BB * (double)HW;
        const double mean = S / P;
        const double var  = Q / P - mean * mean;
        const float rstd  = (float)(1.0 / sqrt(var + (double)BN_EPS));
        const float sc = gam[c] * rstd;
        outSc[c] = sc;
        outSh[c] = bet[c] - (float)mean * sc;
    }
}

// Decoder path: finalize from fused per-block partials.
__global__ __launch_bounds__(256)
void bn_finalize2(const float* __restrict__ gam, const float* __restrict__ bet,
                  int HW, int B, float* __restrict__ outSc,
                  float* __restrict__ outSh)
{
    const int c = blockIdx.x;
    double S = 0.0, Q = 0.0;
    for (int t = threadIdx.x; t < B; t += 256) {
        const float2 p = g_stats[c * MAXB + t];
        S += (double)p.x; Q += (double)p.y;
    }
    __shared__ double sS[256], sQ[256];
    sS[threadIdx.x] = S; sQ[threadIdx.x] = Q;
    __syncthreads();
    for (int off = 128; off; off >>= 1) {
        if (threadIdx.x < off) {
            sS[threadIdx.x] += sS[threadIdx.x + off];
            sQ[threadIdx.x] += sQ[threadIdx.x + off];
        }
        __syncthreads();
    }
    if (threadIdx.x == 0) {
        const double P = (double)BB * (double)HW;
        const double mean = sS[0] / P;
        const double var  = sQ[0] / P - mean * mean;
        const float rstd  = (float)(1.0 / sqrt(var + (double)BN_EPS));
        const float sc = gam[c] * rstd;
        outSc[c] = sc;
        outSh[c] = bet[c] - (float)mean * sc;
    }
}

__global__ __launch_bounds__(256)
void bn_apply_tanh(float* __restrict__ x, int C, int HW, int total4,
                   const float* __restrict__ sc_, const float* __restrict__ sh_)
{
    const int i = blockIdx.x * 256 + threadIdx.x;
    if (i >= total4) return;
    const int hw4 = HW >> 2;
    const int c = (i / hw4) % C;
    const float sc = sc_[c], sh = sh_[c];
    float4 v = ((float4*)x)[i];
    v.x = tanhf(fmaf(v.x, sc, sh)); v.y = tanhf(fmaf(v.y, sc, sh));
    v.z = tanhf(fmaf(v.z, sc, sh)); v.w = tanhf(fmaf(v.w, sc, sh));
    ((float4*)x)[i] = v;
}

// ---------------------------------- VQ -------------------------------------
__global__ void code_norms(const float* __restrict__ cb)
{
    const int k = threadIdx.x;
    float s = 0.f;
    const float* r = cb + k * 64;
    #pragma unroll
    for (int d = 0; d < 64; d++) s = fmaf(r[d], r[d], s);
    g_codeNorm[k] = s;
}

__global__ __launch_bounds__(128)
void vq_argmin(const float* __restrict__ ze, const float* __restrict__ cb,
               const float* __restrict__ sc_, const float* __restrict__ sh_)
{
    __shared__ float sc[64 * 64];
    __shared__ float scn[64];
    __shared__ float red[128];
    __shared__ float ssc[64], ssh[64];

    if (threadIdx.x < 64) {
        ssc[threadIdx.x] = sc_[threadIdx.x];
        ssh[threadIdx.x] = sh_[threadIdx.x];
    }
    __syncthreads();

    const int idx = blockIdx.x * 128 + threadIdx.x;
    const int n  = idx >> 10;
    const int hw = idx & 1023;
    const float* base = ze + (long long)n * 64 * 1024 + hw;

    float z[64];
    #pragma unroll
    for (int d = 0; d < 64; d++)
        z[d] = fmaxf(0.f, fmaf(base[d * 1024], ssc[d], ssh[d]));
    float zz = 0.f;
    #pragma unroll
    for (int d = 0; d < 64; d++) zz = fmaf(z[d], z[d], zz);

    float best = 3.4e38f;
    int   bi   = 0;
    for (int ch = 0; ch < 8; ch++) {
        __syncthreads();
        for (int t = threadIdx.x; t < 1024; t += 128)
            ((float4*)sc)[t] = ((const float4*)(cb + ch * 4096))[t];
        if (threadIdx.x < 64) scn[threadIdx.x] = g_codeNorm[ch * 64 + threadIdx.x];
        __syncthreads();
        #pragma unroll 2
        for (int j = 0; j < 64; j++) {
            const float4* cp = (const float4*)&sc[j * 64];
            float dot = 0.f;
            #pragma unroll
            for (int d4 = 0; d4 < 16; d4++) {
                float4 c4 = cp[d4];
                dot = fmaf(z[4*d4+0], c4.x, dot);
                dot = fmaf(z[4*d4+1], c4.y, dot);
                dot = fmaf(z[4*d4+2], c4.z, dot);
                dot = fmaf(z[4*d4+3], c4.w, dot);
            }
            const float dist = zz - 2.f * dot + scn[j];
            const int k = ch * 64 + j;
            if (dist < best) { best = dist; bi = k; }
        }
    }
    g_idx[idx] = bi;

    const float* cr = cb + bi * 64;
    float e = 0.f;
    #pragma unroll
    for (int d = 0; d < 64; d++) { float df = z[d] - cr[d]; e = fmaf(df, df, e); }

    red[threadIdx.x] = e;
    __syncthreads();
    for (int off = 64; off; off >>= 1) {
        if (threadIdx.x < off) red[threadIdx.x] += red[threadIdx.x + off];
        __syncthreads();
    }
    if (threadIdx.x == 0) g_lossPart[blockIdx.x] = red[0];
}

__global__ void vq_loss_final(float* __restrict__ loss_out)
{
    __shared__ double red[512];
    red[threadIdx.x] = (double)g_lossPart[threadIdx.x];
    __syncthreads();
    for (int off = 256; off; off >>= 1) {
        if (threadIdx.x < off) red[threadIdx.x] += red[threadIdx.x + off];
        __syncthreads();
    }
    if (threadIdx.x == 0)
        loss_out[0] = (float)(2.0 * red[0] / (65536.0 * 64.0));
}

// -------------------------------- launch -----------------------------------
static inline int nblk(long long total) { return (int)((total + 255) / 256); }

extern "C" void kernel_launch(void* const* d_in, const int* in_sizes, int n_in,
                              void* d_out, int out_size)
{
    (void)in_sizes; (void)n_in;
    const float* x    = (const float*)d_in[0];
    const float* cb   = (const float*)d_in[1];
    const float* eW1  = (const float*)d_in[2];
    const float* eb1  = (const float*)d_in[3];
    const float* eg1  = (const float*)d_in[4];
    const float* ebt1 = (const float*)d_in[5];
    const float* eW2  = (const float*)d_in[6];
    const float* eb2  = (const float*)d_in[7];
    const float* eg2  = (const float*)d_in[8];
    const float* ebt2 = (const float*)d_in[9];
    const float* eW3  = (const float*)d_in[10];
    const float* eb3  = (const float*)d_in[11];
    const float* eg3  = (const float*)d_in[12];
    const float* ebt3 = (const float*)d_in[13];
    const float* dW1  = (const float*)d_in[14];
    const float* db1  = (const float*)d_in[15];
    const float* dg1  = (const float*)d_in[16];
    const float* dbt1 = (const float*)d_in[17];
    const float* dW2  = (const float*)d_in[18];
    const float* db2  = (const float*)d_in[19];
    const float* dg2  = (const float*)d_in[20];
    const float* dbt2 = (const float*)d_in[21];
    const float* dW3  = (const float*)d_in[22];
    const float* db3  = (const float*)d_in[23];
    const float* dg3  = (const float*)d_in[24];
    const float* dbt3 = (const float*)d_in[25];
    float* out = (float*)d_out;

    float *a1, *a2, *a3, *d1, *d2, *bnSc, *bnSh;
    int* idxp;
    cudaGetSymbolAddress((void**)&a1, g_a1);
    cudaGetSymbolAddress((void**)&a2, g_a2);
    cudaGetSymbolAddress((void**)&a3, g_a3);
    cudaGetSymbolAddress((void**)&d1, g_d1);
    cudaGetSymbolAddress((void**)&d2, g_d2);
    cudaGetSymbolAddress((void**)&bnSc, g_bnSc);
    cudaGetSymbolAddress((void**)&bnSh, g_bnSh);
    cudaGetSymbolAddress((void**)&idxp, g_idx);
    #define SLOT(i) (bnSc + (i) * 64), (bnSh + (i) * 64)

    // ---------------- encoder (scalar fp32, bit-exact BN stats) ------------
    conv_q<3, 16, 16, 3, 256, 256, false><<<dim3(2048, 1), 128>>>(
        x, eW1, eb1, a1, nullptr, nullptr);
    bn_stats<<<16 * 32, 256>>>(a1, 16, 128 * 128);
    bn_finalize<<<16, 32>>>(eg1, ebt1, 128 * 128, SLOT(0));

    conv_q<16, 32, 16, 2, 128, 128, true><<<dim3(512, 2), 128>>>(
        a1, eW2, eb2, a2, SLOT(0));
    bn_stats<<<32 * 32, 256>>>(a2, 32, 64 * 64);
    bn_finalize<<<32, 32>>>(eg2, ebt2, 64 * 64, SLOT(1));

    conv_q<32, 64, 16, 2, 64, 64, true><<<dim3(128, 4), 128>>>(
        a2, eW3, eb3, a3, SLOT(1));
    bn_stats<<<64 * 32, 256>>>(a3, 64, 32 * 32);
    bn_finalize<<<64, 32>>>(eg3, ebt3, 32 * 32, SLOT(2));

    // ---------------- vector quantization (exact fp32) ----------------
    code_norms<<<1, 512>>>(cb);
    vq_argmin<<<512, 128>>>(a3, cb, SLOT(2));
    vq_loss_final<<<1, 512>>>(out + (out_size - 1));

    // ---------------- decoder (TF32 mma, fused stats) ----------------
    deconv_mma<64, 32, 4, 8, 32, 32, false, true><<<512, 256>>>(
        cb, dW1, db1, d1, nullptr, nullptr, idxp);
    bn_finalize2<<<32, 256>>>(dg1, dbt1, 64 * 64, 512, SLOT(3));

    deconv_mma<32, 16, 2, 16, 64, 64, true, false><<<2048, 256>>>(
        d1, dW2, db2, d2, SLOT(3), nullptr);
    bn_finalize2<<<16, 256>>>(dg2, dbt2, 128 * 128, 2048, SLOT(4));

    deconv_mma<16, 3, 1, 16, 128, 128, true, false><<<8192, 256>>>(
        d2, dW3, db3, out, SLOT(4), nullptr);
    {
        const long long T = (long long)BB * 3 * 256 * 256;
        bn_finalize2<<<3, 256>>>(dg3, dbt3, 256 * 256, 8192, SLOT(5));
        bn_apply_tanh<<<nblk(T / 4), 256>>>(out, 3, 256 * 256, (int)(T / 4), SLOT(5));
    }
    #undef SLOT
}

// round 16
// speedup vs baseline: 1.1619x; 1.0068x over previous
#include <cuda_runtime.h>
#include <math.h>

// ---------------------------------------------------------------------------
// VQ-VAE forward. Encoder: scalar fp32 (bit-exact chain — argmin-safe).
// VQ: exact scalar fp32 argmin (chain-invariant). Decoder: TF32 mma with
// fused BN statistics; deconv1 gathers codebook directly.
// ---------------------------------------------------------------------------

#define BB 64
#define MAXB 8192
static const float BN_EPS = 1e-5f;

// ------------------------- scratch (device globals) ------------------------
__device__ float g_a1[64 * 16 * 128 * 128];
__device__ float g_a2[64 * 32 * 64 * 64];
__device__ float g_a3[64 * 64 * 32 * 32];
__device__ float g_d1[64 * 32 * 64 * 64];
__device__ float g_d2[64 * 16 * 128 * 128];

__device__ int    g_idx[65536];
__device__ float  g_codeNorm[512];
__device__ float2 g_part[64 * 32];        // encoder slab partials (bit-exact)
__device__ float2 g_stats[64 * MAXB];     // decoder per-block partials
__device__ float  g_bnSc[6 * 64];
__device__ float  g_bnSh[6 * 64];
__device__ float  g_lossPart[512];

// ---------------------------- f32x2 helpers --------------------------------
__device__ __forceinline__ unsigned long long splat2(float v) {
    unsigned long long r;
    asm("mov.b64 %0, {%1, %1};" : "=l"(r) : "r"(__float_as_uint(v)));
    return r;
}
__device__ __forceinline__ unsigned long long pack2(float a, float b) {
    unsigned long long r;
    asm("mov.b64 %0, {%1, %2};" : "=l"(r)
        : "r"(__float_as_uint(a)), "r"(__float_as_uint(b)));
    return r;
}
__device__ __forceinline__ void unpack2(unsigned long long p, float& a, float& b) {
    unsigned int lo, hi;
    asm("mov.b64 {%0, %1}, %2;" : "=r"(lo), "=r"(hi) : "l"(p));
    a = __uint_as_float(lo); b = __uint_as_float(hi);
}
__device__ __forceinline__ void fma2(unsigned long long& acc,
                                     unsigned long long a, unsigned long long b) {
    asm("fma.rn.f32x2 %0, %1, %2, %0;" : "+l"(acc) : "l"(a), "l"(b));
}

// ---------------------------- tf32 mma helpers -----------------------------
__device__ __forceinline__ unsigned int f2tf(float x) {
    unsigned int r;
    asm("cvt.rna.tf32.f32 %0, %1;" : "=r"(r) : "f"(x));
    return r;
}
__device__ __forceinline__ void mma_tf32(float* c, const unsigned int* a,
                                         const unsigned int* b) {
    asm volatile(
        "mma.sync.aligned.m16n8k8.row.col.f32.tf32.tf32.f32 "
        "{%0,%1,%2,%3}, {%4,%5,%6,%7}, {%8,%9}, {%0,%1,%2,%3};"
        : "+f"(c[0]), "+f"(c[1]), "+f"(c[2]), "+f"(c[3])
        : "r"(a[0]), "r"(a[1]), "r"(a[2]), "r"(a[3]), "r"(b[0]), "r"(b[1]));
}

// ------------------------------ conv k4 s2 p1 (scalar, encoder) ------------
// Accumulation order per output: ci ascending (chunking-invariant), ky, kx.
template <int CIN, int COUT, int COUTG, int CICHUNK, int HIN, int WIN, bool FUSE>
__global__ __launch_bounds__(128, 5)
void conv_q(const float* __restrict__ in, const float* __restrict__ w,
            const float* __restrict__ bias, float* __restrict__ out,
            const float* __restrict__ bnsc, const float* __restrict__ bnsh)
{
    constexpr int HOUT = HIN / 2, WOUT = WIN / 2;
    constexpr int NBX = WOUT / 32, NBY = HOUT / 16;
    constexpr int TR = 34, TC = 66, TP = 68;

    __shared__ __align__(16) float tile[CICHUNK][TR][TP];
    __shared__ __align__(16) float ws[CICHUNK * 16 * COUTG];

    const int b  = blockIdx.x;
    const int tx = b % NBX;
    const int ty = (b / NBX) % NBY;
    const int n  = b / (NBX * NBY);
    const int cog = blockIdx.y * COUTG;
    const int lx = threadIdx.x & 15, ly = threadIdx.x >> 4;

    const int X0 = tx * 64 - 1, Y0 = ty * 32 - 1;
    const float* inn = in + (long long)n * CIN * HIN * WIN;

    unsigned long long acc[4][COUTG / 2];
    #pragma unroll
    for (int j = 0; j < COUTG / 2; j++) {
        const unsigned long long bp =
            pack2(__ldg(&bias[cog + 2 * j]), __ldg(&bias[cog + 2 * j + 1]));
        acc[0][j] = bp; acc[1][j] = bp; acc[2][j] = bp; acc[3][j] = bp;
    }

    for (int ci0 = 0; ci0 < CIN; ci0 += CICHUNK) {
        __syncthreads();
        for (int t = threadIdx.x; t < COUTG * CICHUNK * 16; t += 128) {
            const int j  = t % COUTG;
            const int kk = t / COUTG;
            ws[t] = w[(cog + j) * CIN * 16 + ci0 * 16 + kk];
        }
        for (int t = threadIdx.x; t < CICHUNK * TR * TC; t += 128) {
            const int c  = t / (TR * TC);
            const int r  = (t / TC) % TR;
            const int cc = t % TC;
            const int gyy = Y0 + r, gxx = X0 + cc;
            const bool ok = ((unsigned)gyy < (unsigned)HIN) &&
                            ((unsigned)gxx < (unsigned)WIN);
            float v = ok ?
                __ldg(&inn[((long long)(ci0 + c) * HIN + gyy) * WIN + gxx]) : 0.f;
            if (FUSE && ok)
                v = fmaxf(0.f, fmaf(v, bnsc[ci0 + c], bnsh[ci0 + c]));
            tile[c][r][cc] = v;
        }
        __syncthreads();

        #pragma unroll
        for (int cil = 0; cil < CICHUNK; cil++) {
            #pragma unroll
            for (int ky = 0; ky < 4; ky++) {
                float ra[6], rb[6];
                {
                    const float4 a4 = *(const float4*)&tile[cil][4*ly+ky][4*lx];
                    const float2 a2 = *(const float2*)&tile[cil][4*ly+ky][4*lx+4];
                    ra[0]=a4.x; ra[1]=a4.y; ra[2]=a4.z; ra[3]=a4.w; ra[4]=a2.x; ra[5]=a2.y;
                    const float4 b4 = *(const float4*)&tile[cil][4*ly+2+ky][4*lx];
                    const float2 b2 = *(const float2*)&tile[cil][4*ly+2+ky][4*lx+4];
                    rb[0]=b4.x; rb[1]=b4.y; rb[2]=b4.z; rb[3]=b4.w; rb[4]=b2.x; rb[5]=b2.y;
                }
                #pragma unroll
                for (int kx = 0; kx < 4; kx++) {
                    const ulonglong2* w8 =
                        (const ulonglong2*)&ws[(cil * 16 + ky * 4 + kx) * COUTG];
                    ulonglong2 wv[COUTG / 4];
                    #pragma unroll
                    for (int q = 0; q < COUTG / 4; q++) wv[q] = w8[q];
                    #pragma unroll
                    for (int ix = 0; ix < 2; ix++) {
                        const unsigned long long tA = splat2(ra[2 * ix + kx]);
                        const unsigned long long tB = splat2(rb[2 * ix + kx]);
                        #pragma unroll
                        for (int q = 0; q < COUTG / 4; q++) {
                            fma2(acc[ix][2 * q + 0], tA, wv[q].x);
                            fma2(acc[ix][2 * q + 1], tA, wv[q].y);
                            fma2(acc[2 + ix][2 * q + 0], tB, wv[q].x);
                            fma2(acc[2 + ix][2 * q + 1], tB, wv[q].y);
                        }
                    }
                }
            }
        }
    }

    const int oy = ty * 16 + 2 * ly, ox = tx * 32 + 2 * lx;
    #pragma unroll
    for (int j = 0; j < COUTG; j++) {
        float v00, v01, v10, v11, tA, tB;
        unpack2(acc[0][j >> 1], tA, tB); v00 = (j & 1) ? tB : tA;
        unpack2(acc[1][j >> 1], tA, tB); v01 = (j & 1) ? tB : tA;
        unpack2(acc[2][j >> 1], tA, tB); v10 = (j & 1) ? tB : tA;
        unpack2(acc[3][j >> 1], tA, tB); v11 = (j & 1) ? tB : tA;
        const long long cb = (long long)n * COUT + cog + j;
        *(float2*)&out[(cb * HOUT + oy) * WOUT + ox]     = make_float2(v00, v01);
        *(float2*)&out[(cb * HOUT + oy + 1) * WOUT + ox] = make_float2(v10, v11);
    }
}

// --------------------- deconv k4 s2 p1 via TF32 mma ------------------------
template <int CIN, int COUT, int NT, int KC, int HIN, int WIN, bool FUSE, bool GATHER>
__global__ __launch_bounds__(256)
void deconv_mma(const float* __restrict__ in, const float* __restrict__ w,
                const float* __restrict__ bias, float* __restrict__ out,
                const float* __restrict__ bnsc, const float* __restrict__ bnsh,
                const int* __restrict__ idxp)
{
    constexpr int COPAD = COUT + 8;
    constexpr int HOUT = 2 * HIN, WOUT = 2 * WIN;
    constexpr int NBX = WIN / 16, NBY = HIN / 8;

    __shared__ unsigned int tile[KC][10][20];
    __shared__ unsigned int wB[16 * KC * COPAD];
    __shared__ int codes[10 * 20];
    __shared__ float sred[8][4][4][4];

    const int b  = blockIdx.x;
    const int tx = b % NBX;
    const int ty = (b / NBX) % NBY;
    const int n  = b / (NBX * NBY);
    const int X0 = tx * 16, Y0 = ty * 8;

    const int lane = threadIdx.x & 31;
    const int wid  = threadIdx.x >> 5;
    const int px = wid & 1, py = (wid >> 1) & 1, h = wid >> 2;

    const float* inn = in + (GATHER ? 0 : (long long)n * CIN * HIN * WIN);

    if (GATHER) {
        for (int t = threadIdx.x; t < 10 * 18; t += 256) {
            const int r = t / 18, cc = t % 18;
            const int gy = Y0 - 1 + r, gx = X0 - 1 + cc;
            const bool ok = ((unsigned)gy < (unsigned)HIN) &&
                            ((unsigned)gx < (unsigned)WIN);
            codes[r * 20 + cc] = ok ? idxp[n * (HIN * WIN) + gy * WIN + gx] : -1;
        }
    }

    float acc[4][NT][4];
    #pragma unroll
    for (int nt = 0; nt < NT; nt++) {
        const int co0 = nt * 8 + 2 * (lane & 3);
        const float b0 = (co0     < COUT) ? __ldg(&bias[co0])     : 0.f;
        const float b1 = (co0 + 1 < COUT) ? __ldg(&bias[co0 + 1]) : 0.f;
        #pragma unroll
        for (int mt = 0; mt < 4; mt++) {
            acc[mt][nt][0] = b0; acc[mt][nt][1] = b1;
            acc[mt][nt][2] = b0; acc[mt][nt][3] = b1;
        }
    }

    for (int ci0 = 0; ci0 < CIN; ci0 += KC) {
        __syncthreads();
        for (int t = threadIdx.x; t < 16 * KC * COPAD; t += 256) {
            const int co  = t % COPAD;
            const int rem = t / COPAD;
            const int ci  = rem % KC;
            const int tap = rem / KC;
            const float v = (co < COUT) ?
                __ldg(&w[(co * CIN + ci0 + ci) * 16 + tap]) : 0.f;
            wB[t] = f2tf(v);
        }
        for (int t = threadIdx.x; t < KC * 10 * 18; t += 256) {
            const int cc  = t % 18;
            const int rem = t / 18;
            const int r   = rem % 10;
            const int c   = rem / 10;
            float v = 0.f;
            if (GATHER) {
                const int code = codes[r * 20 + cc];
                if (code >= 0) v = __ldg(&in[code * 64 + ci0 + c]);
            } else {
                const int gy = Y0 - 1 + r, gx = X0 - 1 + cc;
                const bool ok = ((unsigned)gy < (unsigned)HIN) &&
                                ((unsigned)gx < (unsigned)WIN);
                if (ok) {
                    v = __ldg(&inn[((long long)(ci0 + c) * HIN + gy) * WIN + gx]);
                    if (FUSE)
                        v = fmaxf(0.f, fmaf(v, bnsc[ci0 + c], bnsh[ci0 + c]));
                }
            }
            tile[c][r][cc] = f2tf(v);
        }
        __syncthreads();

        #pragma unroll
        for (int a = 0; a < 2; a++) {
            #pragma unroll
            for (int bs = 0; bs < 2; bs++) {
                const int tap = (py + 2 * a) * 4 + (px + 2 * bs);
                const unsigned int* wT = &wB[tap * KC * COPAD];
                const int xA = (lane >> 2) + px + bs;
                #pragma unroll
                for (int kk = 0; kk < KC / 8; kk++) {
                    const int kA = kk * 8 + (lane & 3);
                    unsigned int A[4][4];
                    #pragma unroll
                    for (int mt = 0; mt < 4; mt++) {
                        const int yA = h * 4 + mt + py + a;
                        A[mt][0] = tile[kA][yA][xA];
                        A[mt][1] = tile[kA][yA][xA + 8];
                        A[mt][2] = tile[kA + 4][yA][xA];
                        A[mt][3] = tile[kA + 4][yA][xA + 8];
                    }
                    #pragma unroll
                    for (int nt = 0; nt < NT; nt++) {
                        unsigned int Bf[2];
                        const int coL = nt * 8 + (lane >> 2);
                        Bf[0] = wT[kA * COPAD + coL];
                        Bf[1] = wT[(kA + 4) * COPAD + coL];
                        #pragma unroll
                        for (int mt = 0; mt < 4; mt++)
                            mma_tf32(acc[mt][nt], A[mt], Bf);
                    }
                }
            }
        }
    }

    #pragma unroll
    for (int mt = 0; mt < 4; mt++) {
        const int orow = 2 * (Y0 + h * 4 + mt) + py;
        const int qx0 = lane >> 2;
        const int ox0 = 2 * (X0 + qx0) + px;
        const int ox1 = 2 * (X0 + qx0 + 8) + px;
        #pragma unroll
        for (int nt = 0; nt < NT; nt++) {
            const int co0 = nt * 8 + 2 * (lane & 3);
            if (co0 < COUT) {
                float* rowp = out + (((long long)n * COUT + co0) * HOUT + orow) * WOUT;
                rowp[ox0] = acc[mt][nt][0];
                rowp[ox1] = acc[mt][nt][2];
            }
            if (co0 + 1 < COUT) {
                float* rowp = out + (((long long)n * COUT + co0 + 1) * HOUT + orow) * WOUT;
                rowp[ox0] = acc[mt][nt][1];
                rowp[ox1] = acc[mt][nt][3];
            }
        }
    }

    // ---- fused BN statistics (deterministic; decoder only) ----
    {
        const int l = lane & 3;
        #pragma unroll
        for (int nt = 0; nt < NT; nt++) {
            float s0 = 0.f, q0 = 0.f, s1 = 0.f, q1 = 0.f;
            #pragma unroll
            for (int mt = 0; mt < 4; mt++) {
                const float a0 = acc[mt][nt][0], a2 = acc[mt][nt][2];
                const float a1 = acc[mt][nt][1], a3 = acc[mt][nt][3];
                s0 += a0 + a2; q0 += a0 * a0 + a2 * a2;
                s1 += a1 + a3; q1 += a1 * a1 + a3 * a3;
            }
            #pragma unroll
            for (int off = 4; off < 32; off <<= 1) {
                s0 += __shfl_xor_sync(0xffffffffu, s0, off);
                q0 += __shfl_xor_sync(0xffffffffu, q0, off);
                s1 += __shfl_xor_sync(0xffffffffu, s1, off);
                q1 += __shfl_xor_sync(0xffffffffu, q1, off);
            }
            if ((lane >> 2) == 0) {
                sred[wid][nt][l][0] = s0; sred[wid][nt][l][1] = q0;
                sred[wid][nt][l][2] = s1; sred[wid][nt][l][3] = q1;
            }
        }
        __syncthreads();
        if (threadIdx.x < 4 * NT) {
            const int nt = threadIdx.x >> 2, l2 = threadIdx.x & 3;
            float s0 = 0.f, q0 = 0.f, s1 = 0.f, q1 = 0.f;
            #pragma unroll
            for (int w2 = 0; w2 < 8; w2++) {
                s0 += sred[w2][nt][l2][0]; q0 += sred[w2][nt][l2][1];
                s1 += sred[w2][nt][l2][2]; q1 += sred[w2][nt][l2][3];
            }
            const int ch0 = nt * 8 + 2 * l2;
            if (ch0 < COUT)     g_stats[ch0 * MAXB + blockIdx.x] = make_float2(s0, q0);
            if (ch0 + 1 < COUT) g_stats[(ch0 + 1) * MAXB + blockIdx.x] = make_float2(s1, q1);
        }
    }
}

// ------------------------------- batchnorm ---------------------------------
__global__ __launch_bounds__(256)
void bn_stats(const float* __restrict__ x, int C, int HW)
{
    const int c = blockIdx.x >> 5;
    const int s = blockIdx.x & 31;
    const int chunk4 = HW >> 7;

    float sum = 0.f, sq = 0.f;
    for (int n = 0; n < BB; n++) {
        const float4* base = (const float4*)(x + ((long long)(n * C + c)) * HW) +
                             s * chunk4;
        for (int p = threadIdx.x; p < chunk4; p += 256) {
            float4 v = base[p];
            sum += v.x + v.y + v.z + v.w;
            sq = fmaf(v.x, v.x, sq); sq = fmaf(v.y, v.y, sq);
            sq = fmaf(v.z, v.z, sq); sq = fmaf(v.w, v.w, sq);
        }
    }
    __shared__ float s1[256], s2[256];
    s1[threadIdx.x] = sum; s2[threadIdx.x] = sq;
    __syncthreads();
    for (int off = 128; off; off >>= 1) {
        if (threadIdx.x < off) {
            s1[threadIdx.x] += s1[threadIdx.x + off];
            s2[threadIdx.x] += s2[threadIdx.x + off];
        }
        __syncthreads();
    }
    if (threadIdx.x == 0) g_part[blockIdx.x] = make_float2(s1[0], s2[0]);
}

__global__ void bn_finalize(const float* __restrict__ gam,
                            const float* __restrict__ bet, int HW,
                            float* __restrict__ outSc, float* __restrict__ outSh)
{
    const int c = blockIdx.x;
    float2 p = g_part[c * 32 + threadIdx.x];
    double S = p.x, Q = p.y;
    for (int off = 16; off; off >>= 1) {
        S += __shfl_down_sync(0xffffffffu, S, off);
        Q += __shfl_down_sync(0xffffffffu, Q, off);
    }
    if (threadIdx.x == 0) {
        const double P = (double)BB * (double)HW;
        const double mean = S / P;
        const double var  = Q / P - mean * mean;
        const float rstd  = (float)(1.0 / sqrt(var + (double)BN_EPS));
        const float sc = gam[c] * rstd;
        outSc[c] = sc;
        outSh[c] = bet[c] - (float)mean * sc;
    }
}

__global__ __launch_bounds__(256)
void bn_finalize2(const float* __restrict__ gam, const float* __restrict__ bet,
                  int HW, int B, float* __restrict__ outSc,
                  float* __restrict__ outSh)
{
    const int c = blockIdx.x;
    double S = 0.0, Q = 0.0;
    for (int t = threadIdx.x; t < B; t += 256) {
        const float2 p = g_stats[c * MAXB + t];
        S += (double)p.x; Q += (double)p.y;
    }
    __shared__ double sS[256], sQ[256];
    sS[threadIdx.x] = S; sQ[threadIdx.x] = Q;
    __syncthreads();
    for (int off = 128; off; off >>= 1) {
        if (threadIdx.x < off) {
            sS[threadIdx.x] += sS[threadIdx.x + off];
            sQ[threadIdx.x] += sQ[threadIdx.x + off];
        }
        __syncthreads();
    }
    if (threadIdx.x == 0) {
        const double P = (double)BB * (double)HW;
        const double mean = sS[0] / P;
        const double var  = sQ[0] / P - mean * mean;
        const float rstd  = (float)(1.0 / sqrt(var + (double)BN_EPS));
        const float sc = gam[c] * rstd;
        outSc[c] = sc;
        outSh[c] = bet[c] - (float)mean * sc;
    }
}

__global__ __launch_bounds__(256)
void bn_apply_tanh(float* __restrict__ x, int C, int HW, int total4,
                   const float* __restrict__ sc_, const float* __restrict__ sh_)
{
    const int i = blockIdx.x * 256 + threadIdx.x;
    if (i >= total4) return;
    const int hw4 = HW >> 2;
    const int c = (i / hw4) % C;
    const float sc = sc_[c], sh = sh_[c];
    float4 v = ((float4*)x)[i];
    v.x = tanhf(fmaf(v.x, sc, sh)); v.y = tanhf(fmaf(v.y, sc, sh));
    v.z = tanhf(fmaf(v.z, sc, sh)); v.w = tanhf(fmaf(v.w, sc, sh));
    ((float4*)x)[i] = v;
}

// ---------------------------------- VQ (exact scalar fp32) -----------------
__global__ void code_norms(const float* __restrict__ cb)
{
    const int k = threadIdx.x;
    float s = 0.f;
    const float* r = cb + k * 64;
    #pragma unroll
    for (int d = 0; d < 64; d++) s = fmaf(r[d], r[d], s);
    g_codeNorm[k] = s;
}

__global__ __launch_bounds__(128)
void vq_argmin(const float* __restrict__ ze, const float* __restrict__ cb,
               const float* __restrict__ sc_, const float* __restrict__ sh_)
{
    __shared__ float sc[64 * 64];
    __shared__ float scn[64];
    __shared__ float red[128];
    __shared__ float ssc[64], ssh[64];

    if (threadIdx.x < 64) {
        ssc[threadIdx.x] = sc_[threadIdx.x];
        ssh[threadIdx.x] = sh_[threadIdx.x];
    }
    __syncthreads();

    const int idx = blockIdx.x * 128 + threadIdx.x;
    const int n  = idx >> 10;
    const int hw = idx & 1023;
    const float* base = ze + (long long)n * 64 * 1024 + hw;

    float z[64];
    #pragma unroll
    for (int d = 0; d < 64; d++)
        z[d] = fmaxf(0.f, fmaf(base[d * 1024], ssc[d], ssh[d]));
    float zz = 0.f;
    #pragma unroll
    for (int d = 0; d < 64; d++) zz = fmaf(z[d], z[d], zz);

    float best = 3.4e38f;
    int   bi   = 0;
    for (int ch = 0; ch < 8; ch++) {
        __syncthreads();
        for (int t = threadIdx.x; t < 1024; t += 128)
            ((float4*)sc)[t] = ((const float4*)(cb + ch * 4096))[t];
        if (threadIdx.x < 64) scn[threadIdx.x] = g_codeNorm[ch * 64 + threadIdx.x];
        __syncthreads();
        #pragma unroll 4
        for (int j = 0; j < 64; j++) {
            const float4* cp = (const float4*)&sc[j * 64];
            float dot = 0.f;
            #pragma unroll
            for (int d4 = 0; d4 < 16; d4++) {
                float4 c4 = cp[d4];
                dot = fmaf(z[4*d4+0], c4.x, dot);
                dot = fmaf(z[4*d4+1], c4.y, dot);
                dot = fmaf(z[4*d4+2], c4.z, dot);
                dot = fmaf(z[4*d4+3], c4.w, dot);
            }
            const float dist = zz - 2.f * dot + scn[j];
            const int k = ch * 64 + j;
            if (dist < best) { best = dist; bi = k; }
        }
    }
    g_idx[idx] = bi;

    const float* cr = cb + bi * 64;
    float e = 0.f;
    #pragma unroll
    for (int d = 0; d < 64; d++) { float df = z[d] - cr[d]; e = fmaf(df, df, e); }

    red[threadIdx.x] = e;
    __syncthreads();
    for (int off = 64; off; off >>= 1) {
        if (threadIdx.x < off) red[threadIdx.x] += red[threadIdx.x + off];
        __syncthreads();
    }
    if (threadIdx.x == 0) g_lossPart[blockIdx.x] = red[0];
}

__global__ void vq_loss_final(float* __restrict__ loss_out)
{
    __shared__ double red[512];
    red[threadIdx.x] = (double)g_lossPart[threadIdx.x];
    __syncthreads();
    for (int off = 256; off; off >>= 1) {
        if (threadIdx.x < off) red[threadIdx.x] += red[threadIdx.x + off];
        __syncthreads();
    }
    if (threadIdx.x == 0)
        loss_out[0] = (float)(2.0 * red[0] / (65536.0 * 64.0));
}

// -------------------------------- launch -----------------------------------
static inline int nblk(long long total) { return (int)((total + 255) / 256); }

extern "C" void kernel_launch(void* const* d_in, const int* in_sizes, int n_in,
                              void* d_out, int out_size)
{
    (void)in_sizes; (void)n_in;
    const float* x    = (const float*)d_in[0];
    const float* cb   = (const float*)d_in[1];
    const float* eW1  = (const float*)d_in[2];
    const float* eb1  = (const float*)d_in[3];
    const float* eg1  = (const float*)d_in[4];
    const float* ebt1 = (const float*)d_in[5];
    const float* eW2  = (const float*)d_in[6];
    const float* eb2  = (const float*)d_in[7];
    const float* eg2  = (const float*)d_in[8];
    const float* ebt2 = (const float*)d_in[9];
    const float* eW3  = (const float*)d_in[10];
    const float* eb3  = (const float*)d_in[11];
    const float* eg3  = (const float*)d_in[12];
    const float* ebt3 = (const float*)d_in[13];
    const float* dW1  = (const float*)d_in[14];
    const float* db1  = (const float*)d_in[15];
    const float* dg1  = (const float*)d_in[16];
    const float* dbt1 = (const float*)d_in[17];
    const float* dW2  = (const float*)d_in[18];
    const float* db2  = (const float*)d_in[19];
    const float* dg2  = (const float*)d_in[20];
    const float* dbt2 = (const float*)d_in[21];
    const float* dW3  = (const float*)d_in[22];
    const float* db3  = (const float*)d_in[23];
    const float* dg3  = (const float*)d_in[24];
    const float* dbt3 = (const float*)d_in[25];
    float* out = (float*)d_out;

    float *a1, *a2, *a3, *d1, *d2, *bnSc, *bnSh;
    int* idxp;
    cudaGetSymbolAddress((void**)&a1, g_a1);
    cudaGetSymbolAddress((void**)&a2, g_a2);
    cudaGetSymbolAddress((void**)&a3, g_a3);
    cudaGetSymbolAddress((void**)&d1, g_d1);
    cudaGetSymbolAddress((void**)&d2, g_d2);
    cudaGetSymbolAddress((void**)&bnSc, g_bnSc);
    cudaGetSymbolAddress((void**)&bnSh, g_bnSh);
    cudaGetSymbolAddress((void**)&idxp, g_idx);
    #define SLOT(i) (bnSc + (i) * 64), (bnSh + (i) * 64)

    // ---------------- encoder (scalar fp32, bit-exact chain) ---------------
    conv_q<3, 16, 16, 3, 256, 256, false><<<dim3(2048, 1), 128>>>(
        x, eW1, eb1, a1, nullptr, nullptr);
    bn_stats<<<16 * 32, 256>>>(a1, 16, 128 * 128);
    bn_finalize<<<16, 32>>>(eg1, ebt1, 128 * 128, SLOT(0));

    conv_q<16, 32, 16, 4, 128, 128, true><<<dim3(512, 2), 128>>>(
        a1, eW2, eb2, a2, SLOT(0));
    bn_stats<<<32 * 32, 256>>>(a2, 32, 64 * 64);
    bn_finalize<<<32, 32>>>(eg2, ebt2, 64 * 64, SLOT(1));

    conv_q<32, 64, 16, 4, 64, 64, true><<<dim3(128, 4), 128>>>(
        a2, eW3, eb3, a3, SLOT(1));
    bn_stats<<<64 * 32, 256>>>(a3, 64, 32 * 32);
    bn_finalize<<<64, 32>>>(eg3, ebt3, 32 * 32, SLOT(2));

    // ---------------- vector quantization (exact fp32) ----------------
    code_norms<<<1, 512>>>(cb);
    vq_argmin<<<512, 128>>>(a3, cb, SLOT(2));
    vq_loss_final<<<1, 512>>>(out + (out_size - 1));

    // ---------------- decoder (TF32 mma, fused stats) ----------------
    deconv_mma<64, 32, 4, 8, 32, 32, false, true><<<512, 256>>>(
        cb, dW1, db1, d1, nullptr, nullptr, idxp);
    bn_finalize2<<<32, 256>>>(dg1, dbt1, 64 * 64, 512, SLOT(3));

    deconv_mma<32, 16, 2, 16, 64, 64, true, false><<<2048, 256>>>(
        d1, dW2, db2, d2, SLOT(3), nullptr);
    bn_finalize2<<<16, 256>>>(dg2, dbt2, 128 * 128, 2048, SLOT(4));

    deconv_mma<16, 3, 1, 16, 128, 128, true, false><<<8192, 256>>>(
        d2, dW3, db3, out, SLOT(4), nullptr);
    {
        const long long T = (long long)BB * 3 * 256 * 256;
        bn_finalize2<<<3, 256>>>(dg3, dbt3, 256 * 256, 8192, SLOT(5));
        bn_apply_tanh<<<nblk(T / 4), 256>>>(out, 3, 256 * 256, (int)(T / 4), SLOT(5));
    }
    #undef SLOT
}

// round 17
// speedup vs baseline: 1.1678x; 1.0051x over previous
#include <cuda_runtime.h>
#include <math.h>

// ---------------------------------------------------------------------------
// VQ-VAE forward. Encoder: scalar fp32 (bit-exact chain — argmin-safe).
// VQ: exact fp32 argmin with f32x2-paired codes (bit-identical per-code
// chains). Decoder: TF32 mma with fused BN statistics; deconv1 gathers
// codebook directly.
// ---------------------------------------------------------------------------

#define BB 64
#define MAXB 8192
static const float BN_EPS = 1e-5f;

// ------------------------- scratch (device globals) ------------------------
__device__ float g_a1[64 * 16 * 128 * 128];
__device__ float g_a2[64 * 32 * 64 * 64];
__device__ float g_a3[64 * 64 * 32 * 32];
__device__ float g_d1[64 * 32 * 64 * 64];
__device__ float g_d2[64 * 16 * 128 * 128];

__device__ int    g_idx[65536];
__device__ float  g_codeNorm[512];
__device__ float2 g_part[64 * 32];        // encoder slab partials (bit-exact)
__device__ float2 g_stats[64 * MAXB];     // decoder per-block partials
__device__ float  g_bnSc[6 * 64];
__device__ float  g_bnSh[6 * 64];
__device__ float  g_lossPart[512];

// ---------------------------- f32x2 helpers --------------------------------
__device__ __forceinline__ unsigned long long splat2(float v) {
    unsigned long long r;
    asm("mov.b64 %0, {%1, %1};" : "=l"(r) : "r"(__float_as_uint(v)));
    return r;
}
__device__ __forceinline__ unsigned long long pack2(float a, float b) {
    unsigned long long r;
    asm("mov.b64 %0, {%1, %2};" : "=l"(r)
        : "r"(__float_as_uint(a)), "r"(__float_as_uint(b)));
    return r;
}
__device__ __forceinline__ void unpack2(unsigned long long p, float& a, float& b) {
    unsigned int lo, hi;
    asm("mov.b64 {%0, %1}, %2;" : "=r"(lo), "=r"(hi) : "l"(p));
    a = __uint_as_float(lo); b = __uint_as_float(hi);
}
__device__ __forceinline__ void fma2(unsigned long long& acc,
                                     unsigned long long a, unsigned long long b) {
    asm("fma.rn.f32x2 %0, %1, %2, %0;" : "+l"(acc) : "l"(a), "l"(b));
}

// ---------------------------- tf32 mma helpers -----------------------------
__device__ __forceinline__ unsigned int f2tf(float x) {
    unsigned int r;
    asm("cvt.rna.tf32.f32 %0, %1;" : "=r"(r) : "f"(x));
    return r;
}
__device__ __forceinline__ void mma_tf32(float* c, const unsigned int* a,
                                         const unsigned int* b) {
    asm volatile(
        "mma.sync.aligned.m16n8k8.row.col.f32.tf32.tf32.f32 "
        "{%0,%1,%2,%3}, {%4,%5,%6,%7}, {%8,%9}, {%0,%1,%2,%3};"
        : "+f"(c[0]), "+f"(c[1]), "+f"(c[2]), "+f"(c[3])
        : "r"(a[0]), "r"(a[1]), "r"(a[2]), "r"(a[3]), "r"(b[0]), "r"(b[1]));
}

// ------------------------------ conv k4 s2 p1 (scalar, encoder) ------------
template <int CIN, int COUT, int COUTG, int CICHUNK, int HIN, int WIN, bool FUSE>
__global__ __launch_bounds__(128, 5)
void conv_q(const float* __restrict__ in, const float* __restrict__ w,
            const float* __restrict__ bias, float* __restrict__ out,
            const float* __restrict__ bnsc, const float* __restrict__ bnsh)
{
    constexpr int HOUT = HIN / 2, WOUT = WIN / 2;
    constexpr int NBX = WOUT / 32, NBY = HOUT / 16;
    constexpr int TR = 34, TC = 66, TP = 68;

    __shared__ __align__(16) float tile[CICHUNK][TR][TP];
    __shared__ __align__(16) float ws[CICHUNK * 16 * COUTG];

    const int b  = blockIdx.x;
    const int tx = b % NBX;
    const int ty = (b / NBX) % NBY;
    const int n  = b / (NBX * NBY);
    const int cog = blockIdx.y * COUTG;
    const int lx = threadIdx.x & 15, ly = threadIdx.x >> 4;

    const int X0 = tx * 64 - 1, Y0 = ty * 32 - 1;
    const float* inn = in + (long long)n * CIN * HIN * WIN;

    unsigned long long acc[4][COUTG / 2];
    #pragma unroll
    for (int j = 0; j < COUTG / 2; j++) {
        const unsigned long long bp =
            pack2(__ldg(&bias[cog + 2 * j]), __ldg(&bias[cog + 2 * j + 1]));
        acc[0][j] = bp; acc[1][j] = bp; acc[2][j] = bp; acc[3][j] = bp;
    }

    for (int ci0 = 0; ci0 < CIN; ci0 += CICHUNK) {
        __syncthreads();
        for (int t = threadIdx.x; t < COUTG * CICHUNK * 16; t += 128) {
            const int j  = t % COUTG;
            const int kk = t / COUTG;
            ws[t] = w[(cog + j) * CIN * 16 + ci0 * 16 + kk];
        }
        for (int t = threadIdx.x; t < CICHUNK * TR * TC; t += 128) {
            const int c  = t / (TR * TC);
            const int r  = (t / TC) % TR;
            const int cc = t % TC;
            const int gyy = Y0 + r, gxx = X0 + cc;
            const bool ok = ((unsigned)gyy < (unsigned)HIN) &&
                            ((unsigned)gxx < (unsigned)WIN);
            float v = ok ?
                __ldg(&inn[((long long)(ci0 + c) * HIN + gyy) * WIN + gxx]) : 0.f;
            if (FUSE && ok)
                v = fmaxf(0.f, fmaf(v, bnsc[ci0 + c], bnsh[ci0 + c]));
            tile[c][r][cc] = v;
        }
        __syncthreads();

        #pragma unroll
        for (int cil = 0; cil < CICHUNK; cil++) {
            #pragma unroll
            for (int ky = 0; ky < 4; ky++) {
                float ra[6], rb[6];
                {
                    const float4 a4 = *(const float4*)&tile[cil][4*ly+ky][4*lx];
                    const float2 a2 = *(const float2*)&tile[cil][4*ly+ky][4*lx+4];
                    ra[0]=a4.x; ra[1]=a4.y; ra[2]=a4.z; ra[3]=a4.w; ra[4]=a2.x; ra[5]=a2.y;
                    const float4 b4 = *(const float4*)&tile[cil][4*ly+2+ky][4*lx];
                    const float2 b2 = *(const float2*)&tile[cil][4*ly+2+ky][4*lx+4];
                    rb[0]=b4.x; rb[1]=b4.y; rb[2]=b4.z; rb[3]=b4.w; rb[4]=b2.x; rb[5]=b2.y;
                }
                #pragma unroll
                for (int kx = 0; kx < 4; kx++) {
                    const ulonglong2* w8 =
                        (const ulonglong2*)&ws[(cil * 16 + ky * 4 + kx) * COUTG];
                    ulonglong2 wv[COUTG / 4];
                    #pragma unroll
                    for (int q = 0; q < COUTG / 4; q++) wv[q] = w8[q];
                    #pragma unroll
                    for (int ix = 0; ix < 2; ix++) {
                        const unsigned long long tA = splat2(ra[2 * ix + kx]);
                        const unsigned long long tB = splat2(rb[2 * ix + kx]);
                        #pragma unroll
                        for (int q = 0; q < COUTG / 4; q++) {
                            fma2(acc[ix][2 * q + 0], tA, wv[q].x);
                            fma2(acc[ix][2 * q + 1], tA, wv[q].y);
                            fma2(acc[2 + ix][2 * q + 0], tB, wv[q].x);
                            fma2(acc[2 + ix][2 * q + 1], tB, wv[q].y);
                        }
                    }
                }
            }
        }
    }

    const int oy = ty * 16 + 2 * ly, ox = tx * 32 + 2 * lx;
    #pragma unroll
    for (int j = 0; j < COUTG; j++) {
        float v00, v01, v10, v11, tA, tB;
        unpack2(acc[0][j >> 1], tA, tB); v00 = (j & 1) ? tB : tA;
        unpack2(acc[1][j >> 1], tA, tB); v01 = (j & 1) ? tB : tA;
        unpack2(acc[2][j >> 1], tA, tB); v10 = (j & 1) ? tB : tA;
        unpack2(acc[3][j >> 1], tA, tB); v11 = (j & 1) ? tB : tA;
        const long long cb = (long long)n * COUT + cog + j;
        *(float2*)&out[(cb * HOUT + oy) * WOUT + ox]     = make_float2(v00, v01);
        *(float2*)&out[(cb * HOUT + oy + 1) * WOUT + ox] = make_float2(v10, v11);
    }
}

// --------------------- deconv k4 s2 p1 via TF32 mma ------------------------
template <int CIN, int COUT, int NT, int KC, int HIN, int WIN, bool FUSE, bool GATHER>
__global__ __launch_bounds__(256)
void deconv_mma(const float* __restrict__ in, const float* __restrict__ w,
                const float* __restrict__ bias, float* __restrict__ out,
                const float* __restrict__ bnsc, const float* __restrict__ bnsh,
                const int* __restrict__ idxp)
{
    constexpr int COPAD = COUT + 8;
    constexpr int HOUT = 2 * HIN, WOUT = 2 * WIN;
    constexpr int NBX = WIN / 16, NBY = HIN / 8;

    __shared__ unsigned int tile[KC][10][20];
    __shared__ unsigned int wB[16 * KC * COPAD];
    __shared__ int codes[10 * 20];
    __shared__ float sred[8][4][4][4];

    const int b  = blockIdx.x;
    const int tx = b % NBX;
    const int ty = (b / NBX) % NBY;
    const int n  = b / (NBX * NBY);
    const int X0 = tx * 16, Y0 = ty * 8;

    const int lane = threadIdx.x & 31;
    const int wid  = threadIdx.x >> 5;
    const int px = wid & 1, py = (wid >> 1) & 1, h = wid >> 2;

    const float* inn = in + (GATHER ? 0 : (long long)n * CIN * HIN * WIN);

    if (GATHER) {
        for (int t = threadIdx.x; t < 10 * 18; t += 256) {
            const int r = t / 18, cc = t % 18;
            const int gy = Y0 - 1 + r, gx = X0 - 1 + cc;
            const bool ok = ((unsigned)gy < (unsigned)HIN) &&
                            ((unsigned)gx < (unsigned)WIN);
            codes[r * 20 + cc] = ok ? idxp[n * (HIN * WIN) + gy * WIN + gx] : -1;
        }
    }

    float acc[4][NT][4];
    #pragma unroll
    for (int nt = 0; nt < NT; nt++) {
        const int co0 = nt * 8 + 2 * (lane & 3);
        const float b0 = (co0     < COUT) ? __ldg(&bias[co0])     : 0.f;
        const float b1 = (co0 + 1 < COUT) ? __ldg(&bias[co0 + 1]) : 0.f;
        #pragma unroll
        for (int mt = 0; mt < 4; mt++) {
            acc[mt][nt][0] = b0; acc[mt][nt][1] = b1;
            acc[mt][nt][2] = b0; acc[mt][nt][3] = b1;
        }
    }

    for (int ci0 = 0; ci0 < CIN; ci0 += KC) {
        __syncthreads();
        for (int t = threadIdx.x; t < 16 * KC * COPAD; t += 256) {
            const int co  = t % COPAD;
            const int rem = t / COPAD;
            const int ci  = rem % KC;
            const int tap = rem / KC;
            const float v = (co < COUT) ?
                __ldg(&w[(co * CIN + ci0 + ci) * 16 + tap]) : 0.f;
            wB[t] = f2tf(v);
        }
        for (int t = threadIdx.x; t < KC * 10 * 18; t += 256) {
            const int cc  = t % 18;
            const int rem = t / 18;
            const int r   = rem % 10;
            const int c   = rem / 10;
            float v = 0.f;
            if (GATHER) {
                const int code = codes[r * 20 + cc];
                if (code >= 0) v = __ldg(&in[code * 64 + ci0 + c]);
            } else {
                const int gy = Y0 - 1 + r, gx = X0 - 1 + cc;
                const bool ok = ((unsigned)gy < (unsigned)HIN) &&
                                ((unsigned)gx < (unsigned)WIN);
                if (ok) {
                    v = __ldg(&inn[((long long)(ci0 + c) * HIN + gy) * WIN + gx]);
                    if (FUSE)
                        v = fmaxf(0.f, fmaf(v, bnsc[ci0 + c], bnsh[ci0 + c]));
                }
            }
            tile[c][r][cc] = f2tf(v);
        }
        __syncthreads();

        #pragma unroll
        for (int a = 0; a < 2; a++) {
            #pragma unroll
            for (int bs = 0; bs < 2; bs++) {
                const int tap = (py + 2 * a) * 4 + (px + 2 * bs);
                const unsigned int* wT = &wB[tap * KC * COPAD];
                const int xA = (lane >> 2) + px + bs;
                #pragma unroll
                for (int kk = 0; kk < KC / 8; kk++) {
                    const int kA = kk * 8 + (lane & 3);
                    unsigned int A[4][4];
                    #pragma unroll
                    for (int mt = 0; mt < 4; mt++) {
                        const int yA = h * 4 + mt + py + a;
                        A[mt][0] = tile[kA][yA][xA];
                        A[mt][1] = tile[kA][yA][xA + 8];
                        A[mt][2] = tile[kA + 4][yA][xA];
                        A[mt][3] = tile[kA + 4][yA][xA + 8];
                    }
                    #pragma unroll
                    for (int nt = 0; nt < NT; nt++) {
                        unsigned int Bf[2];
                        const int coL = nt * 8 + (lane >> 2);
                        Bf[0] = wT[kA * COPAD + coL];
                        Bf[1] = wT[(kA + 4) * COPAD + coL];
                        #pragma unroll
                        for (int mt = 0; mt < 4; mt++)
                            mma_tf32(acc[mt][nt], A[mt], Bf);
                    }
                }
            }
        }
    }

    #pragma unroll
    for (int mt = 0; mt < 4; mt++) {
        const int orow = 2 * (Y0 + h * 4 + mt) + py;
        const int qx0 = lane >> 2;
        const int ox0 = 2 * (X0 + qx0) + px;
        const int ox1 = 2 * (X0 + qx0 + 8) + px;
        #pragma unroll
        for (int nt = 0; nt < NT; nt++) {
            const int co0 = nt * 8 + 2 * (lane & 3);
            if (co0 < COUT) {
                float* rowp = out + (((long long)n * COUT + co0) * HOUT + orow) * WOUT;
                rowp[ox0] = acc[mt][nt][0];
                rowp[ox1] = acc[mt][nt][2];
            }
            if (co0 + 1 < COUT) {
                float* rowp = out + (((long long)n * COUT + co0 + 1) * HOUT + orow) * WOUT;
                rowp[ox0] = acc[mt][nt][1];
                rowp[ox1] = acc[mt][nt][3];
            }
        }
    }

    // ---- fused BN statistics (deterministic; decoder only) ----
    {
        const int l = lane & 3;
        #pragma unroll
        for (int nt = 0; nt < NT; nt++) {
            float s0 = 0.f, q0 = 0.f, s1 = 0.f, q1 = 0.f;
            #pragma unroll
            for (int mt = 0; mt < 4; mt++) {
                const float a0 = acc[mt][nt][0], a2 = acc[mt][nt][2];
                const float a1 = acc[mt][nt][1], a3 = acc[mt][nt][3];
                s0 += a0 + a2; q0 += a0 * a0 + a2 * a2;
                s1 += a1 + a3; q1 += a1 * a1 + a3 * a3;
            }
            #pragma unroll
            for (int off = 4; off < 32; off <<= 1) {
                s0 += __shfl_xor_sync(0xffffffffu, s0, off);
                q0 += __shfl_xor_sync(0xffffffffu, q0, off);
                s1 += __shfl_xor_sync(0xffffffffu, s1, off);
                q1 += __shfl_xor_sync(0xffffffffu, q1, off);
            }
            if ((lane >> 2) == 0) {
                sred[wid][nt][l][0] = s0; sred[wid][nt][l][1] = q0;
                sred[wid][nt][l][2] = s1; sred[wid][nt][l][3] = q1;
            }
        }
        __syncthreads();
        if (threadIdx.x < 4 * NT) {
            const int nt = threadIdx.x >> 2, l2 = threadIdx.x & 3;
            float s0 = 0.f, q0 = 0.f, s1 = 0.f, q1 = 0.f;
            #pragma unroll
            for (int w2 = 0; w2 < 8; w2++) {
                s0 += sred[w2][nt][l2][0]; q0 += sred[w2][nt][l2][1];
                s1 += sred[w2][nt][l2][2]; q1 += sred[w2][nt][l2][3];
            }
            const int ch0 = nt * 8 + 2 * l2;
            if (ch0 < COUT)     g_stats[ch0 * MAXB + blockIdx.x] = make_float2(s0, q0);
            if (ch0 + 1 < COUT) g_stats[(ch0 + 1) * MAXB + blockIdx.x] = make_float2(s1, q1);
        }
    }
}

// ------------------------------- batchnorm ---------------------------------
__global__ __launch_bounds__(256)
void bn_stats(const float* __restrict__ x, int C, int HW)
{
    const int c = blockIdx.x >> 5;
    const int s = blockIdx.x & 31;
    const int chunk4 = HW >> 7;

    float sum = 0.f, sq = 0.f;
    for (int n = 0; n < BB; n++) {
        const float4* base = (const float4*)(x + ((long long)(n * C + c)) * HW) +
                             s * chunk4;
        for (int p = threadIdx.x; p < chunk4; p += 256) {
            float4 v = base[p];
            sum += v.x + v.y + v.z + v.w;
            sq = fmaf(v.x, v.x, sq); sq = fmaf(v.y, v.y, sq);
            sq = fmaf(v.z, v.z, sq); sq = fmaf(v.w, v.w, sq);
        }
    }
    __shared__ float s1[256], s2[256];
    s1[threadIdx.x] = sum; s2[threadIdx.x] = sq;
    __syncthreads();
    for (int off = 128; off; off >>= 1) {
        if (threadIdx.x < off) {
            s1[threadIdx.x] += s1[threadIdx.x + off];
            s2[threadIdx.x] += s2[threadIdx.x + off];
        }
        __syncthreads();
    }
    if (threadIdx.x == 0) g_part[blockIdx.x] = make_float2(s1[0], s2[0]);
}

__global__ void bn_finalize(const float* __restrict__ gam,
                            const float* __restrict__ bet, int HW,
                            float* __restrict__ outSc, float* __restrict__ outSh)
{
    const int c = blockIdx.x;
    float2 p = g_part[c * 32 + threadIdx.x];
    double S = p.x, Q = p.y;
    for (int off = 16; off; off >>= 1) {
        S += __shfl_down_sync(0xffffffffu, S, off);
        Q += __shfl_down_sync(0xffffffffu, Q, off);
    }
    if (threadIdx.x == 0) {
        const double P = (double)BB * (double)HW;
        const double mean = S / P;
        const double var  = Q / P - mean * mean;
        const float rstd  = (float)(1.0 / sqrt(var + (double)BN_EPS));
        const float sc = gam[c] * rstd;
        outSc[c] = sc;
        outSh[c] = bet[c] - (float)mean * sc;
    }
}

__global__ __launch_bounds__(256)
void bn_finalize2(const float* __restrict__ gam, const float* __restrict__ bet,
                  int HW, int B, float* __restrict__ outSc,
                  float* __restrict__ outSh)
{
    const int c = blockIdx.x;
    double S = 0.0, Q = 0.0;
    for (int t = threadIdx.x; t < B; t += 256) {
        const float2 p = g_stats[c * MAXB + t];
        S += (double)p.x; Q += (double)p.y;
    }
    __shared__ double sS[256], sQ[256];
    sS[threadIdx.x] = S; sQ[threadIdx.x] = Q;
    __syncthreads();
    for (int off = 128; off; off >>= 1) {
        if (threadIdx.x < off) {
            sS[threadIdx.x] += sS[threadIdx.x + off];
            sQ[threadIdx.x] += sQ[threadIdx.x + off];
        }
        __syncthreads();
    }
    if (threadIdx.x == 0) {
        const double P = (double)BB * (double)HW;
        const double mean = sS[0] / P;
        const double var  = sQ[0] / P - mean * mean;
        const float rstd  = (float)(1.0 / sqrt(var + (double)BN_EPS));
        const float sc = gam[c] * rstd;
        outSc[c] = sc;
        outSh[c] = bet[c] - (float)mean * sc;
    }
}

__global__ __launch_bounds__(256)
void bn_apply_tanh(float* __restrict__ x, int C, int HW, int total4,
                   const float* __restrict__ sc_, const float* __restrict__ sh_)
{
    const int i = blockIdx.x * 256 + threadIdx.x;
    if (i >= total4) return;
    const int hw4 = HW >> 2;
    const int c = (i / hw4) % C;
    const float sc = sc_[c], sh = sh_[c];
    float4 v = ((float4*)x)[i];
    v.x = tanhf(fmaf(v.x, sc, sh)); v.y = tanhf(fmaf(v.y, sc, sh));
    v.z = tanhf(fmaf(v.z, sc, sh)); v.w = tanhf(fmaf(v.w, sc, sh));
    ((float4*)x)[i] = v;
}

// ---------------------------------- VQ (exact fp32, f32x2 pairs) -----------
__global__ void code_norms(const float* __restrict__ cb)
{
    const int k = threadIdx.x;
    float s = 0.f;
    const float* r = cb + k * 64;
    #pragma unroll
    for (int d = 0; d < 64; d++) s = fmaf(r[d], r[d], s);
    g_codeNorm[k] = s;
}

__global__ __launch_bounds__(128)
void vq_argmin(const float* __restrict__ ze, const float* __restrict__ cb,
               const float* __restrict__ sc_, const float* __restrict__ sh_)
{
    // pair-interleaved codebook chunk: spk[p*64 + d] = (c_{2p}[d], c_{2p+1}[d])
    __shared__ __align__(16) float2 spk[32 * 64];
    __shared__ float scn[64];
    __shared__ float red[128];
    __shared__ float ssc[64], ssh[64];

    if (threadIdx.x < 64) {
        ssc[threadIdx.x] = sc_[threadIdx.x];
        ssh[threadIdx.x] = sh_[threadIdx.x];
    }
    __syncthreads();

    const int idx = blockIdx.x * 128 + threadIdx.x;
    const int n  = idx >> 10;
    const int hw = idx & 1023;
    const float* base = ze + (long long)n * 64 * 1024 + hw;

    float z[64];
    #pragma unroll
    for (int d = 0; d < 64; d++)
        z[d] = fmaxf(0.f, fmaf(base[d * 1024], ssc[d], ssh[d]));
    float zz = 0.f;
    #pragma unroll
    for (int d = 0; d < 64; d++) zz = fmaf(z[d], z[d], zz);

    float best = 3.4e38f;
    int   bi   = 0;
    for (int ch = 0; ch < 8; ch++) {
        __syncthreads();
        for (int i = threadIdx.x; i < 2048; i += 128) {
            const int p = i >> 6, d = i & 63;
            spk[p * 64 + d] = make_float2(
                __ldg(&cb[(ch * 64 + 2 * p) * 64 + d]),
                __ldg(&cb[(ch * 64 + 2 * p + 1) * 64 + d]));
        }
        if (threadIdx.x < 64) scn[threadIdx.x] = g_codeNorm[ch * 64 + threadIdx.x];
        __syncthreads();

        #pragma unroll 2
        for (int p = 0; p < 32; p++) {
            const ulonglong2* pp = (const ulonglong2*)&spk[p * 64];
            unsigned long long acc2 = pack2(0.f, 0.f);
            #pragma unroll
            for (int dq = 0; dq < 32; dq++) {
                const ulonglong2 u = pp[dq];
                fma2(acc2, splat2(z[2 * dq]), u.x);
                fma2(acc2, splat2(z[2 * dq + 1]), u.y);
            }
            float dj, dj1; unpack2(acc2, dj, dj1);
            const int j0 = ch * 64 + 2 * p;
            const float dist0 = zz - 2.f * dj + scn[2 * p];
            if (dist0 < best) { best = dist0; bi = j0; }
            const float dist1 = zz - 2.f * dj1 + scn[2 * p + 1];
            if (dist1 < best) { best = dist1; bi = j0 + 1; }
        }
    }
    g_idx[idx] = bi;

    const float* cr = cb + bi * 64;
    float e = 0.f;
    #pragma unroll
    for (int d = 0; d < 64; d++) { float df = z[d] - cr[d]; e = fmaf(df, df, e); }

    red[threadIdx.x] = e;
    __syncthreads();
    for (int off = 64; off; off >>= 1) {
        if (threadIdx.x < off) red[threadIdx.x] += red[threadIdx.x + off];
        __syncthreads();
    }
    if (threadIdx.x == 0) g_lossPart[blockIdx.x] = red[0];
}

__global__ void vq_loss_final(float* __restrict__ loss_out)
{
    __shared__ double red[512];
    red[threadIdx.x] = (double)g_lossPart[threadIdx.x];
    __syncthreads();
    for (int off = 256; off; off >>= 1) {
        if (threadIdx.x < off) red[threadIdx.x] += red[threadIdx.x + off];
        __syncthreads();
    }
    if (threadIdx.x == 0)
        loss_out[0] = (float)(2.0 * red[0] / (65536.0 * 64.0));
}

// -------------------------------- launch -----------------------------------
static inline int nblk(long long total) { return (int)((total + 255) / 256); }

extern "C" void kernel_launch(void* const* d_in, const int* in_sizes, int n_in,
                              void* d_out, int out_size)
{
    (void)in_sizes; (void)n_in;
    const float* x    = (const float*)d_in[0];
    const float* cb   = (const float*)d_in[1];
    const float* eW1  = (const float*)d_in[2];
    const float* eb1  = (const float*)d_in[3];
    const float* eg1  = (const float*)d_in[4];
    const float* ebt1 = (const float*)d_in[5];
    const float* eW2  = (const float*)d_in[6];
    const float* eb2  = (const float*)d_in[7];
    const float* eg2  = (const float*)d_in[8];
    const float* ebt2 = (const float*)d_in[9];
    const float* eW3  = (const float*)d_in[10];
    const float* eb3  = (const float*)d_in[11];
    const float* eg3  = (const float*)d_in[12];
    const float* ebt3 = (const float*)d_in[13];
    const float* dW1  = (const float*)d_in[14];
    const float* db1  = (const float*)d_in[15];
    const float* dg1  = (const float*)d_in[16];
    const float* dbt1 = (const float*)d_in[17];
    const float* dW2  = (const float*)d_in[18];
    const float* db2  = (const float*)d_in[19];
    const float* dg2  = (const float*)d_in[20];
    const float* dbt2 = (const float*)d_in[21];
    const float* dW3  = (const float*)d_in[22];
    const float* db3  = (const float*)d_in[23];
    const float* dg3  = (const float*)d_in[24];
    const float* dbt3 = (const float*)d_in[25];
    float* out = (float*)d_out;

    float *a1, *a2, *a3, *d1, *d2, *bnSc, *bnSh;
    int* idxp;
    cudaGetSymbolAddress((void**)&a1, g_a1);
    cudaGetSymbolAddress((void**)&a2, g_a2);
    cudaGetSymbolAddress((void**)&a3, g_a3);
    cudaGetSymbolAddress((void**)&d1, g_d1);
    cudaGetSymbolAddress((void**)&d2, g_d2);
    cudaGetSymbolAddress((void**)&bnSc, g_bnSc);
    cudaGetSymbolAddress((void**)&bnSh, g_bnSh);
    cudaGetSymbolAddress((void**)&idxp, g_idx);
    #define SLOT(i) (bnSc + (i) * 64), (bnSh + (i) * 64)

    // ---------------- encoder (scalar fp32, bit-exact chain) ---------------
    conv_q<3, 16, 16, 3, 256, 256, false><<<dim3(2048, 1), 128>>>(
        x, eW1, eb1, a1, nullptr, nullptr);
    bn_stats<<<16 * 32, 256>>>(a1, 16, 128 * 128);
    bn_finalize<<<16, 32>>>(eg1, ebt1, 128 * 128, SLOT(0));

    conv_q<16, 32, 16, 4, 128, 128, true><<<dim3(512, 2), 128>>>(
        a1, eW2, eb2, a2, SLOT(0));
    bn_stats<<<32 * 32, 256>>>(a2, 32, 64 * 64);
    bn_finalize<<<32, 32>>>(eg2, ebt2, 64 * 64, SLOT(1));

    conv_q<32, 64, 16, 4, 64, 64, true><<<dim3(128, 4), 128>>>(
        a2, eW3, eb3, a3, SLOT(1));
    bn_stats<<<64 * 32, 256>>>(a3, 64, 32 * 32);
    bn_finalize<<<64, 32>>>(eg3, ebt3, 32 * 32, SLOT(2));

    // ---------------- vector quantization (exact fp32, f32x2 pairs) --------
    code_norms<<<1, 512>>>(cb);
    vq_argmin<<<512, 128>>>(a3, cb, SLOT(2));
    vq_loss_final<<<1, 512>>>(out + (out_size - 1));

    // ---------------- decoder (TF32 mma, fused stats) ----------------
    deconv_mma<64, 32, 4, 8, 32, 32, false, true><<<512, 256>>>(
        cb, dW1, db1, d1, nullptr, nullptr, idxp);
    bn_finalize2<<<32, 256>>>(dg1, dbt1, 64 * 64, 512, SLOT(3));

    deconv_mma<32, 16, 2, 16, 64, 64, true, false><<<2048, 256>>>(
        d1, dW2, db2, d2, SLOT(3), nullptr);
    bn_finalize2<<<16, 256>>>(dg2, dbt2, 128 * 128, 2048, SLOT(4));

    deconv_mma<16, 3, 1, 16, 128, 128, true, false><<<8192, 256>>>(
        d2, dW3, db3, out, SLOT(4), nullptr);
    {
        const long long T = (long long)BB * 3 * 256 * 256;
        bn_finalize2<<<3, 256>>>(dg3, dbt3, 256 * 256, 8192, SLOT(5));
        bn_apply_tanh<<<nblk(T / 4), 256>>>(out, 3, 256 * 256, (int)(T / 4), SLOT(5));
    }
    #undef SLOT
}